// round 4
// baseline (speedup 1.0000x reference)
#include <cuda_runtime.h>
#include <cuda_bf16.h>

#define BB 4
#define NN 2048
#define CC 768
#define HH 12
#define DD 64
#define MTOT (BB*NN)          /* 8192 */
#define SCALE_Q 0.125f        /* 64^-0.5 */

// ---------------- scratch (no allocation allowed) ----------------
__device__ float g_q [MTOT*CC];
__device__ float g_k [MTOT*CC];
__device__ float g_v [MTOT*CC];
__device__ float g_ao[MTOT*CC];
__device__ float g_uc[MTOT];

// ---------------- uc = mean(x_u, axis=-1), one warp per row ----------------
__global__ void uc_kernel(const float* __restrict__ xu)
{
    int gid  = blockIdx.x * blockDim.x + threadIdx.x;
    int row  = gid >> 5;
    int lane = gid & 31;
    if (row >= MTOT) return;
    const float* p = xu + (size_t)row * CC;
    float s = 0.f;
    #pragma unroll
    for (int i = 0; i < CC/32; i++) s += p[lane + 32*i];
    #pragma unroll
    for (int off = 16; off; off >>= 1) s += __shfl_down_sync(0xffffffffu, s, off);
    if (lane == 0) g_uc[row] = s * (1.0f / (float)CC);
}

// ---------------- Y = X @ W^T, optional per-row scale & bias ----------------
// X:[M,768] row-major, W:[768,768] row-major (out dim = row).
// Tile: BM=128, BN=64, BK=16, 256 threads, 8x4 microtile.
__global__ __launch_bounds__(256)
void gemm_xwt(const float* __restrict__ X, const float* __restrict__ W,
              float* __restrict__ Y,
              const float* __restrict__ rowScale, float scaleConst,
              const float* __restrict__ bias)
{
    __shared__ float As[16][132];   // [k][m], padded
    __shared__ float Bs[16][68];    // [k][n], padded

    const int tid  = threadIdx.x;
    const int m0   = blockIdx.y * 128;
    const int n0   = blockIdx.x * 64;
    const int trow = tid >> 4;      // 0..15 -> 8 rows each
    const int tcol = tid & 15;      // 0..15 -> 4 cols each

    float acc[8][4];
    #pragma unroll
    for (int i = 0; i < 8; i++)
        #pragma unroll
        for (int j = 0; j < 4; j++) acc[i][j] = 0.f;

    const int aR = tid >> 1;              // 0..127
    const int aK = (tid & 1) * 8;         // k base (0 or 8)
    const int bR = tid >> 2;              // 0..63
    const int bK = (tid & 3) * 4;         // k base (0,4,8,12)

    const float* aG = X + (size_t)(m0 + aR) * CC + aK;
    const float* bG = W + (size_t)(n0 + bR) * CC + bK;

    for (int kt = 0; kt < CC; kt += 16) {
        float4 la0 = *(const float4*)(aG + kt);
        float4 la1 = *(const float4*)(aG + kt + 4);
        float4 lb  = *(const float4*)(bG + kt);
        __syncthreads();
        As[aK+0][aR] = la0.x; As[aK+1][aR] = la0.y;
        As[aK+2][aR] = la0.z; As[aK+3][aR] = la0.w;
        As[aK+4][aR] = la1.x; As[aK+5][aR] = la1.y;
        As[aK+6][aR] = la1.z; As[aK+7][aR] = la1.w;
        Bs[bK+0][bR] = lb.x;  Bs[bK+1][bR] = lb.y;
        Bs[bK+2][bR] = lb.z;  Bs[bK+3][bR] = lb.w;
        __syncthreads();

        #pragma unroll
        for (int k = 0; k < 16; k++) {
            float4 a0 = *(const float4*)&As[k][trow*8];
            float4 a1 = *(const float4*)&As[k][trow*8 + 4];
            float4 bv = *(const float4*)&Bs[k][tcol*4];
            float av[8] = {a0.x,a0.y,a0.z,a0.w,a1.x,a1.y,a1.z,a1.w};
            float bw[4] = {bv.x,bv.y,bv.z,bv.w};
            #pragma unroll
            for (int i = 0; i < 8; i++)
                #pragma unroll
                for (int j = 0; j < 4; j++)
                    acc[i][j] = fmaf(av[i], bw[j], acc[i][j]);
        }
    }

    float bz[4] = {0.f, 0.f, 0.f, 0.f};
    if (bias) {
        #pragma unroll
        for (int j = 0; j < 4; j++) bz[j] = bias[n0 + tcol*4 + j];
    }
    #pragma unroll
    for (int i = 0; i < 8; i++) {
        int m = m0 + trow*8 + i;
        float rs = scaleConst;
        if (rowScale) rs *= rowScale[m];
        float4 o;
        o.x = acc[i][0]*rs + bz[0];
        o.y = acc[i][1]*rs + bz[1];
        o.z = acc[i][2]*rs + bz[2];
        o.w = acc[i][3]*rs + bz[3];
        *(float4*)(Y + (size_t)m * CC + n0 + tcol*4) = o;
    }
}

// ---------------- flash attention, fp32 ----------------
// Q already holds q * SCALE * uc (folded into projection epilogue).
// Per CTA: one (b, h, 64-query block). 128 threads. Key blocks of 32.
__global__ __launch_bounds__(128)
void attn_kernel(const float* __restrict__ Q, const float* __restrict__ K,
                 const float* __restrict__ V, float* __restrict__ O)
{
    __shared__ float Qst[64][64];   // [d][q]
    __shared__ float Kst[64][32];   // [d][kc]
    __shared__ float Vs [32][64];   // [kc][d]
    __shared__ float St [32][64];   // [kc][q]   scores then probabilities
    __shared__ float redM[2][64];
    __shared__ float redS[2][64];
    __shared__ float mS[64], lS[64], alphaS[64];

    const int tid  = threadIdx.x;
    const int b    = blockIdx.z;
    const int h    = blockIdx.y;
    const int n0   = blockIdx.x * 64;
    const int rg   = tid >> 4;      // 0..7  -> 8 query rows each
    const int cg   = tid & 15;      // 0..15
    const int r    = tid & 63;      // softmax: query row
    const int half = tid >> 6;      // softmax: key half

    const float* Qb = Q + ((size_t)b * NN) * CC + h * DD;
    const float* Kb = K + ((size_t)b * NN) * CC + h * DD;
    const float* Vb = V + ((size_t)b * NN) * CC + h * DD;

    // load Q tile transposed: Qst[d][q]
    {
        int row = tid >> 1;
        int fb  = (tid & 1) * 8;
        const float* src = Qb + (size_t)(n0 + row) * CC;
        #pragma unroll
        for (int j = 0; j < 8; j++) {
            float4 v = *(const float4*)(src + (fb + j) * 4);
            int d0 = (fb + j) * 4;
            Qst[d0+0][row] = v.x; Qst[d0+1][row] = v.y;
            Qst[d0+2][row] = v.z; Qst[d0+3][row] = v.w;
        }
    }
    if (tid < 64) { mS[tid] = -1e30f; lS[tid] = 0.f; }

    float accO[8][4];
    #pragma unroll
    for (int i = 0; i < 8; i++)
        #pragma unroll
        for (int j = 0; j < 4; j++) accO[i][j] = 0.f;

    __syncthreads();

    for (int kb = 0; kb < NN/32; kb++) {
        // ---- load K (transposed) and V tiles ----
        {
            int row = tid >> 2;                 // 0..31
            int fb  = (tid & 3) * 4;
            const float* src = Kb + (size_t)(kb*32 + row) * CC;
            #pragma unroll
            for (int j = 0; j < 4; j++) {
                float4 v = *(const float4*)(src + (fb + j) * 4);
                int d0 = (fb + j) * 4;
                Kst[d0+0][row] = v.x; Kst[d0+1][row] = v.y;
                Kst[d0+2][row] = v.z; Kst[d0+3][row] = v.w;
            }
            #pragma unroll
            for (int i = 0; i < 4; i++) {
                int s  = i*128 + tid;
                int vr = s >> 4, c4 = s & 15;
                float4 v = *(const float4*)(Vb + (size_t)(kb*32 + vr) * CC + c4*4);
                *(float4*)&Vs[vr][c4*4] = v;
            }
        }
        __syncthreads();

        // ---- S = Q @ K^T  (per thread: 8 queries x 2 keys) ----
        float accS[8][2];
        #pragma unroll
        for (int i = 0; i < 8; i++) { accS[i][0] = 0.f; accS[i][1] = 0.f; }
        #pragma unroll 8
        for (int d = 0; d < 64; d++) {
            float4 q0 = *(const float4*)&Qst[d][rg*8];
            float4 q1 = *(const float4*)&Qst[d][rg*8 + 4];
            float2 kf = *(const float2*)&Kst[d][cg*2];
            float qv[8] = {q0.x,q0.y,q0.z,q0.w,q1.x,q1.y,q1.z,q1.w};
            #pragma unroll
            for (int i = 0; i < 8; i++) {
                accS[i][0] = fmaf(qv[i], kf.x, accS[i][0]);
                accS[i][1] = fmaf(qv[i], kf.y, accS[i][1]);
            }
        }
        #pragma unroll
        for (int j = 0; j < 2; j++) {
            int c = cg*2 + j;
            *(float4*)&St[c][rg*8]     = make_float4(accS[0][j],accS[1][j],accS[2][j],accS[3][j]);
            *(float4*)&St[c][rg*8 + 4] = make_float4(accS[4][j],accS[5][j],accS[6][j],accS[7][j]);
        }
        __syncthreads();

        // ---- online softmax (2 threads per query row) ----
        float m_old = mS[r];
        float pm = -1e30f;
        #pragma unroll
        for (int kk = 0; kk < 16; kk++) pm = fmaxf(pm, St[half*16 + kk][r]);
        redM[half][r] = pm;
        __syncthreads();
        float mn = fmaxf(m_old, fmaxf(redM[0][r], redM[1][r]));
        float ps = 0.f;
        #pragma unroll
        for (int kk = 0; kk < 16; kk++) {
            int k2 = half*16 + kk;
            float p = __expf(St[k2][r] - mn);
            St[k2][r] = p;
            ps += p;
        }
        redS[half][r] = ps;
        __syncthreads();
        if (half == 0) {
            float alpha = __expf(m_old - mn);
            lS[r] = lS[r]*alpha + redS[0][r] + redS[1][r];
            mS[r] = mn;
            alphaS[r] = alpha;
        }
        __syncthreads();

        // ---- rescale O, then O += P @ V ----
        #pragma unroll
        for (int i = 0; i < 8; i++) {
            float al = alphaS[rg*8 + i];
            #pragma unroll
            for (int j = 0; j < 4; j++) accO[i][j] *= al;
        }
        #pragma unroll 8
        for (int k = 0; k < 32; k++) {
            float4 p0 = *(const float4*)&St[k][rg*8];
            float4 p1 = *(const float4*)&St[k][rg*8 + 4];
            float4 vf = *(const float4*)&Vs[k][cg*4];
            float pv[8] = {p0.x,p0.y,p0.z,p0.w,p1.x,p1.y,p1.z,p1.w};
            float vw[4] = {vf.x,vf.y,vf.z,vf.w};
            #pragma unroll
            for (int i = 0; i < 8; i++)
                #pragma unroll
                for (int j = 0; j < 4; j++)
                    accO[i][j] = fmaf(pv[i], vw[j], accO[i][j]);
        }
        __syncthreads();
    }

    // ---- normalize and write ----
    float* dst = O + ((size_t)(b*NN + n0)) * CC + h * DD;
    #pragma unroll
    for (int i = 0; i < 8; i++) {
        float linv = 1.0f / lS[rg*8 + i];
        float4 o;
        o.x = accO[i][0] * linv;
        o.y = accO[i][1] * linv;
        o.z = accO[i][2] * linv;
        o.w = accO[i][3] * linv;
        *(float4*)(dst + (size_t)(rg*8 + i) * CC + cg*4) = o;
    }
}

// ---------------- launch ----------------
extern "C" void kernel_launch(void* const* d_in, const int* in_sizes, int n_in,
                              void* d_out, int out_size)
{
    const float* x_q = (const float*)d_in[0];
    const float* x_k = (const float*)d_in[1];
    const float* x_v = (const float*)d_in[2];
    const float* x_u = (const float*)d_in[3];
    const float* Wq  = (const float*)d_in[4];
    const float* Wk  = (const float*)d_in[5];
    const float* Wv  = (const float*)d_in[6];
    const float* Wp  = (const float*)d_in[7];
    const float* bp  = (const float*)d_in[8];
    float* out = (float*)d_out;

    float *q, *k, *v, *ao, *uc;
    cudaGetSymbolAddress((void**)&q,  g_q);
    cudaGetSymbolAddress((void**)&k,  g_k);
    cudaGetSymbolAddress((void**)&v,  g_v);
    cudaGetSymbolAddress((void**)&ao, g_ao);
    cudaGetSymbolAddress((void**)&uc, g_uc);

    // per-query uncertainty mean
    uc_kernel<<<(MTOT*32 + 255)/256, 256>>>(x_u);

    // projections: q = (x_q Wq^T) * SCALE * uc[row]; k, v plain
    dim3 ggrid(CC/64, MTOT/128);     // (12, 64)
    gemm_xwt<<<ggrid, 256>>>(x_q, Wq, q, uc, SCALE_Q, nullptr);
    gemm_xwt<<<ggrid, 256>>>(x_k, Wk, k, nullptr, 1.0f, nullptr);
    gemm_xwt<<<ggrid, 256>>>(x_v, Wv, v, nullptr, 1.0f, nullptr);

    // flash attention
    dim3 agrid(NN/64, HH, BB);       // (32, 12, 4) = 1536 CTAs
    attn_kernel<<<agrid, 128>>>(q, k, v, ao);

    // output projection + bias
    gemm_xwt<<<ggrid, 256>>>(ao, Wp, out, nullptr, 1.0f, bp);
}

// round 6
// speedup vs baseline: 2.7371x; 2.7371x over previous
#include <cuda_runtime.h>
#include <cuda_bf16.h>
#include <cstdint>

#define BB 4
#define NN 2048
#define CC 768
#define HH 12
#define DD 64
#define MTOT (BB*NN)          /* 8192 */
#define SCALE_Q 0.125f        /* 64^-0.5 */

// ---------------- scratch (no allocation allowed) ----------------
__device__ float g_q [MTOT*CC];
__device__ float g_k [MTOT*CC];
__device__ float g_v [MTOT*CC];   // holds V TRANSPOSED: [B][H][D][N]
__device__ float g_ao[MTOT*CC];
__device__ float g_uc[MTOT];

// ---------------- tf32 helpers ----------------
__device__ __forceinline__ uint32_t f2tf(float f) {
    uint32_t r;
    asm("cvt.rna.tf32.f32 %0, %1;" : "=r"(r) : "f"(f));
    return r;
}
__device__ __forceinline__ void mma_tf32(float* d, const uint32_t* a, const uint32_t* b, const float* c) {
    asm volatile("mma.sync.aligned.m16n8k8.row.col.f32.tf32.tf32.f32 "
        "{%0,%1,%2,%3}, {%4,%5,%6,%7}, {%8,%9}, {%10,%11,%12,%13};\n"
        : "=f"(d[0]), "=f"(d[1]), "=f"(d[2]), "=f"(d[3])
        : "r"(a[0]), "r"(a[1]), "r"(a[2]), "r"(a[3]),
          "r"(b[0]), "r"(b[1]),
          "f"(c[0]), "f"(c[1]), "f"(c[2]), "f"(c[3]));
}

// ---------------- uc = mean(x_u, axis=-1), one warp per row ----------------
__global__ void uc_kernel(const float* __restrict__ xu)
{
    int gid  = blockIdx.x * blockDim.x + threadIdx.x;
    int row  = gid >> 5;
    int lane = gid & 31;
    if (row >= MTOT) return;
    const float* p = xu + (size_t)row * CC;
    float s = 0.f;
    #pragma unroll
    for (int i = 0; i < CC/32; i++) s += p[lane + 32*i];
    #pragma unroll
    for (int off = 16; off; off >>= 1) s += __shfl_down_sync(0xffffffffu, s, off);
    if (lane == 0) g_uc[row] = s * (1.0f / (float)CC);
}

// ================= tf32 mma GEMM: Y = X @ W^T =================
// X:[M,768] row-major, W:[Nout,768] row-major. BM=128, BN=128, BK=16.
// 256 threads = 8 warps (2 m x 4 n); warp tile 64x32 = 4x4 m16n8 tiles.
// vtMode: write output as V^T layout [B][H][D][N] instead of [M][C].
#define GSTRIDE 20
__global__ __launch_bounds__(256)
void gemm_tc(const float* __restrict__ X, const float* __restrict__ W,
             float* __restrict__ Y,
             const float* __restrict__ rowScale, float scaleConst,
             const float* __restrict__ bias, int vtMode)
{
    __shared__ uint32_t As[2][128][GSTRIDE];
    __shared__ uint32_t Bs[2][128][GSTRIDE];

    const int tid = threadIdx.x;
    const int wid = tid >> 5;
    const int lane = tid & 31;
    const int lq = lane >> 2;     // 0..7
    const int lc = lane & 3;      // 0..3
    const int wm = wid >> 2;      // 0..1
    const int wn = wid & 3;       // 0..3
    const int m0 = blockIdx.y * 128;
    const int n0 = blockIdx.x * 128;

    // copy mapping: idx = tid (+256): row = idx>>2, f4 = idx&3
    const int cr = tid >> 2;          // 0..63
    const int cf = (tid & 3) * 4;     // 0,4,8,12
    const float* pA = X + (size_t)(m0 + cr) * CC + cf;
    const float* pB = W + (size_t)(n0 + cr) * CC + cf;

    float acc[4][4][4];
    #pragma unroll
    for (int i = 0; i < 4; i++)
        #pragma unroll
        for (int j = 0; j < 4; j++)
            #pragma unroll
            for (int t = 0; t < 4; t++) acc[i][j][t] = 0.f;

    // prologue: stage 0
    float4 rA0 = *(const float4*)(pA);
    float4 rA1 = *(const float4*)(pA + (size_t)64 * CC);
    float4 rB0 = *(const float4*)(pB);
    float4 rB1 = *(const float4*)(pB + (size_t)64 * CC);
    As[0][cr   ][cf+0]=f2tf(rA0.x); As[0][cr   ][cf+1]=f2tf(rA0.y); As[0][cr   ][cf+2]=f2tf(rA0.z); As[0][cr   ][cf+3]=f2tf(rA0.w);
    As[0][cr+64][cf+0]=f2tf(rA1.x); As[0][cr+64][cf+1]=f2tf(rA1.y); As[0][cr+64][cf+2]=f2tf(rA1.z); As[0][cr+64][cf+3]=f2tf(rA1.w);
    Bs[0][cr   ][cf+0]=f2tf(rB0.x); Bs[0][cr   ][cf+1]=f2tf(rB0.y); Bs[0][cr   ][cf+2]=f2tf(rB0.z); Bs[0][cr   ][cf+3]=f2tf(rB0.w);
    Bs[0][cr+64][cf+0]=f2tf(rB1.x); Bs[0][cr+64][cf+1]=f2tf(rB1.y); Bs[0][cr+64][cf+2]=f2tf(rB1.z); Bs[0][cr+64][cf+3]=f2tf(rB1.w);
    __syncthreads();

    const int NSTAGE = CC / 16;   // 48
    #pragma unroll 1
    for (int s = 0; s < NSTAGE; s++) {
        int cur = s & 1;
        if (s + 1 < NSTAGE) {
            int ko = (s + 1) * 16;
            rA0 = *(const float4*)(pA + ko);
            rA1 = *(const float4*)(pA + (size_t)64 * CC + ko);
            rB0 = *(const float4*)(pB + ko);
            rB1 = *(const float4*)(pB + (size_t)64 * CC + ko);
        }
        // compute stage s
        #pragma unroll
        for (int kk = 0; kk < 2; kk++) {
            int k0 = kk * 8;
            uint32_t af[4][4];
            #pragma unroll
            for (int mi = 0; mi < 4; mi++) {
                int r = wm*64 + mi*16 + lq;
                af[mi][0] = As[cur][r    ][k0 + lc];
                af[mi][1] = As[cur][r + 8][k0 + lc];
                af[mi][2] = As[cur][r    ][k0 + 4 + lc];
                af[mi][3] = As[cur][r + 8][k0 + 4 + lc];
            }
            #pragma unroll
            for (int nj = 0; nj < 4; nj++) {
                int bn = wn*32 + nj*8 + lq;
                uint32_t bf[2];
                bf[0] = Bs[cur][bn][k0 + lc];
                bf[1] = Bs[cur][bn][k0 + 4 + lc];
                #pragma unroll
                for (int mi = 0; mi < 4; mi++)
                    mma_tf32(acc[mi][nj], af[mi], bf, acc[mi][nj]);
            }
        }
        if (s + 1 < NSTAGE) {
            int nxt = 1 - cur;
            As[nxt][cr   ][cf+0]=f2tf(rA0.x); As[nxt][cr   ][cf+1]=f2tf(rA0.y); As[nxt][cr   ][cf+2]=f2tf(rA0.z); As[nxt][cr   ][cf+3]=f2tf(rA0.w);
            As[nxt][cr+64][cf+0]=f2tf(rA1.x); As[nxt][cr+64][cf+1]=f2tf(rA1.y); As[nxt][cr+64][cf+2]=f2tf(rA1.z); As[nxt][cr+64][cf+3]=f2tf(rA1.w);
            Bs[nxt][cr   ][cf+0]=f2tf(rB0.x); Bs[nxt][cr   ][cf+1]=f2tf(rB0.y); Bs[nxt][cr   ][cf+2]=f2tf(rB0.z); Bs[nxt][cr   ][cf+3]=f2tf(rB0.w);
            Bs[nxt][cr+64][cf+0]=f2tf(rB1.x); Bs[nxt][cr+64][cf+1]=f2tf(rB1.y); Bs[nxt][cr+64][cf+2]=f2tf(rB1.z); Bs[nxt][cr+64][cf+3]=f2tf(rB1.w);
        }
        __syncthreads();
    }

    // epilogue
    #pragma unroll
    for (int mi = 0; mi < 4; mi++) {
        int row0 = m0 + wm*64 + mi*16 + lq;
        int row1 = row0 + 8;
        float rs0 = scaleConst, rs1 = scaleConst;
        if (rowScale) { rs0 *= rowScale[row0]; rs1 *= rowScale[row1]; }
        #pragma unroll
        for (int nj = 0; nj < 4; nj++) {
            int col = n0 + wn*32 + nj*8 + 2*lc;
            float v0 = acc[mi][nj][0]*rs0, v1 = acc[mi][nj][1]*rs0;
            float v2 = acc[mi][nj][2]*rs1, v3 = acc[mi][nj][3]*rs1;
            if (!vtMode) {
                if (bias) { float b0 = bias[col], b1 = bias[col+1]; v0 += b0; v1 += b1; v2 += b0; v3 += b1; }
                *(float2*)(Y + (size_t)row0 * CC + col) = make_float2(v0, v1);
                *(float2*)(Y + (size_t)row1 * CC + col) = make_float2(v2, v3);
            } else {
                // V^T layout: [B][H][D][N]
                int h = col >> 6, d = col & 63;
                int b0i = row0 >> 11, n0i = row0 & 2047;
                int b1i = row1 >> 11, n1i = row1 & 2047;
                float* base0 = Y + ((size_t)(b0i*HH + h)*DD) * NN;
                float* base1 = Y + ((size_t)(b1i*HH + h)*DD) * NN;
                base0[(size_t)d*NN + n0i]     = v0;
                base0[(size_t)(d+1)*NN + n0i] = v1;
                base1[(size_t)d*NN + n1i]     = v2;
                base1[(size_t)(d+1)*NN + n1i] = v3;
            }
        }
    }
}

// ================= flash attention, tf32 mma =================
// grid (NN/64, HH, BB), 128 threads = 4 warps, each warp owns 16 q rows.
// Q[B*N][C] (pre-scaled by SCALE*uc), K[B*N][C], Vt[B][H][D][N], O[B*N][C].
#define ASTRIDE 68
#define ATT_SMEM (4*64*ASTRIDE*4)
__global__ __launch_bounds__(128)
void attn_tc(const float* __restrict__ Q, const float* __restrict__ K,
             const float* __restrict__ Vt, float* __restrict__ O)
{
    extern __shared__ uint32_t sm[];
    uint32_t* Qs = sm;                      // [64][68]  (q, d)
    uint32_t* Ks = sm + 64*ASTRIDE;         // [64][68]  (key, d)
    uint32_t* Vs = sm + 2*64*ASTRIDE;       // [64][68]  (d, key)
    uint32_t* Ps = sm + 3*64*ASTRIDE;       // [64][68]  (q, key)

    const int tid  = threadIdx.x;
    const int wid  = tid >> 5;
    const int lane = tid & 31;
    const int lq   = lane >> 2;
    const int lc   = lane & 3;
    const int wq   = wid * 16;
    const int b    = blockIdx.z;
    const int h    = blockIdx.y;
    const int n0q  = blockIdx.x * 64;

    const float* Qb  = Q + ((size_t)(b*NN + n0q)) * CC + h * DD;
    const float* Kb  = K + ((size_t)b * NN) * CC + h * DD;
    const float* Vtb = Vt + ((size_t)(b*HH + h) * DD) * NN;

    // load Q tile once: Qs[q][d], cvt to tf32
    {
        const int row = tid >> 4;           // advances by 8 per pass
        const int f4  = (tid & 15) * 4;
        #pragma unroll
        for (int i = 0; i < 8; i++) {
            float4 v = *(const float4*)(Qb + (size_t)(row + i*8) * CC + f4);
            uint32_t* d = &Qs[(row + i*8)*ASTRIDE + f4];
            d[0]=f2tf(v.x); d[1]=f2tf(v.y); d[2]=f2tf(v.z); d[3]=f2tf(v.w);
        }
    }

    float oacc[8][4];
    #pragma unroll
    for (int i = 0; i < 8; i++)
        #pragma unroll
        for (int t = 0; t < 4; t++) oacc[i][t] = 0.f;
    float mrow0 = -1e30f, mrow1 = -1e30f, lrow0 = 0.f, lrow1 = 0.f;

    #pragma unroll 1
    for (int kb = 0; kb < NN/64; kb++) {
        // ---- load K tile (key,d) and V tile (d,key) ----
        {
            const int row = tid >> 4;
            const int f4  = (tid & 15) * 4;
            const float* ksrc = Kb + (size_t)(kb*64) * CC;
            #pragma unroll
            for (int i = 0; i < 8; i++) {
                float4 v = *(const float4*)(ksrc + (size_t)(row + i*8) * CC + f4);
                uint32_t* d = &Ks[(row + i*8)*ASTRIDE + f4];
                d[0]=f2tf(v.x); d[1]=f2tf(v.y); d[2]=f2tf(v.z); d[3]=f2tf(v.w);
            }
            #pragma unroll
            for (int i = 0; i < 8; i++) {
                float4 v = *(const float4*)(Vtb + (size_t)(row + i*8) * NN + kb*64 + f4);
                uint32_t* d = &Vs[(row + i*8)*ASTRIDE + f4];
                d[0]=f2tf(v.x); d[1]=f2tf(v.y); d[2]=f2tf(v.z); d[3]=f2tf(v.w);
            }
        }
        __syncthreads();

        // ---- S = Q K^T : 16 q rows x 64 keys per warp ----
        float sacc[8][4];
        #pragma unroll
        for (int i = 0; i < 8; i++)
            #pragma unroll
            for (int t = 0; t < 4; t++) sacc[i][t] = 0.f;
        #pragma unroll
        for (int ks = 0; ks < 8; ks++) {
            int k0 = ks * 8;
            uint32_t af[4];
            af[0] = Qs[(wq + lq    )*ASTRIDE + k0 + lc];
            af[1] = Qs[(wq + lq + 8)*ASTRIDE + k0 + lc];
            af[2] = Qs[(wq + lq    )*ASTRIDE + k0 + 4 + lc];
            af[3] = Qs[(wq + lq + 8)*ASTRIDE + k0 + 4 + lc];
            #pragma unroll
            for (int nt = 0; nt < 8; nt++) {
                uint32_t bf[2];
                bf[0] = Ks[(nt*8 + lq)*ASTRIDE + k0 + lc];
                bf[1] = Ks[(nt*8 + lq)*ASTRIDE + k0 + 4 + lc];
                mma_tf32(sacc[nt], af, bf, sacc[nt]);
            }
        }

        // ---- online softmax (register-resident; quad shuffles) ----
        float rmax0 = -1e30f, rmax1 = -1e30f;
        #pragma unroll
        for (int nt = 0; nt < 8; nt++) {
            rmax0 = fmaxf(rmax0, fmaxf(sacc[nt][0], sacc[nt][1]));
            rmax1 = fmaxf(rmax1, fmaxf(sacc[nt][2], sacc[nt][3]));
        }
        rmax0 = fmaxf(rmax0, __shfl_xor_sync(0xffffffffu, rmax0, 1));
        rmax0 = fmaxf(rmax0, __shfl_xor_sync(0xffffffffu, rmax0, 2));
        rmax1 = fmaxf(rmax1, __shfl_xor_sync(0xffffffffu, rmax1, 1));
        rmax1 = fmaxf(rmax1, __shfl_xor_sync(0xffffffffu, rmax1, 2));
        float nm0 = fmaxf(mrow0, rmax0);
        float nm1 = fmaxf(mrow1, rmax1);
        float al0 = __expf(mrow0 - nm0);
        float al1 = __expf(mrow1 - nm1);
        float sum0 = 0.f, sum1 = 0.f;
        #pragma unroll
        for (int nt = 0; nt < 8; nt++) {
            float p0 = __expf(sacc[nt][0] - nm0);
            float p1 = __expf(sacc[nt][1] - nm0);
            float p2 = __expf(sacc[nt][2] - nm1);
            float p3 = __expf(sacc[nt][3] - nm1);
            sum0 += p0 + p1; sum1 += p2 + p3;
            uint2 u0 = make_uint2(f2tf(p0), f2tf(p1));
            uint2 u1 = make_uint2(f2tf(p2), f2tf(p3));
            *(uint2*)&Ps[(wq + lq    )*ASTRIDE + nt*8 + 2*lc] = u0;
            *(uint2*)&Ps[(wq + lq + 8)*ASTRIDE + nt*8 + 2*lc] = u1;
        }
        sum0 += __shfl_xor_sync(0xffffffffu, sum0, 1);
        sum0 += __shfl_xor_sync(0xffffffffu, sum0, 2);
        sum1 += __shfl_xor_sync(0xffffffffu, sum1, 1);
        sum1 += __shfl_xor_sync(0xffffffffu, sum1, 2);
        lrow0 = lrow0 * al0 + sum0;  mrow0 = nm0;
        lrow1 = lrow1 * al1 + sum1;  mrow1 = nm1;
        #pragma unroll
        for (int nt = 0; nt < 8; nt++) {
            oacc[nt][0] *= al0; oacc[nt][1] *= al0;
            oacc[nt][2] *= al1; oacc[nt][3] *= al1;
        }
        __syncwarp();

        // ---- O += P @ V : contraction over 64 keys ----
        #pragma unroll
        for (int ks = 0; ks < 8; ks++) {
            int k0 = ks * 8;
            uint32_t af[4];
            af[0] = Ps[(wq + lq    )*ASTRIDE + k0 + lc];
            af[1] = Ps[(wq + lq + 8)*ASTRIDE + k0 + lc];
            af[2] = Ps[(wq + lq    )*ASTRIDE + k0 + 4 + lc];
            af[3] = Ps[(wq + lq + 8)*ASTRIDE + k0 + 4 + lc];
            #pragma unroll
            for (int nt = 0; nt < 8; nt++) {
                uint32_t bf[2];
                bf[0] = Vs[(nt*8 + lq)*ASTRIDE + k0 + lc];
                bf[1] = Vs[(nt*8 + lq)*ASTRIDE + k0 + 4 + lc];
                mma_tf32(oacc[nt], af, bf, oacc[nt]);
            }
        }
        __syncthreads();
    }

    // ---- normalize and write ----
    float li0 = 1.0f / lrow0;
    float li1 = 1.0f / lrow1;
    float* dst0 = O + ((size_t)(b*NN + n0q + wq + lq    )) * CC + h * DD;
    float* dst1 = O + ((size_t)(b*NN + n0q + wq + lq + 8)) * CC + h * DD;
    #pragma unroll
    for (int nt = 0; nt < 8; nt++) {
        *(float2*)(dst0 + nt*8 + 2*lc) = make_float2(oacc[nt][0]*li0, oacc[nt][1]*li0);
        *(float2*)(dst1 + nt*8 + 2*lc) = make_float2(oacc[nt][2]*li1, oacc[nt][3]*li1);
    }
}

// ---------------- launch ----------------
extern "C" void kernel_launch(void* const* d_in, const int* in_sizes, int n_in,
                              void* d_out, int out_size)
{
    const float* x_q = (const float*)d_in[0];
    const float* x_k = (const float*)d_in[1];
    const float* x_v = (const float*)d_in[2];
    const float* x_u = (const float*)d_in[3];
    const float* Wq  = (const float*)d_in[4];
    const float* Wk  = (const float*)d_in[5];
    const float* Wv  = (const float*)d_in[6];
    const float* Wp  = (const float*)d_in[7];
    const float* bp  = (const float*)d_in[8];
    float* out = (float*)d_out;

    float *q, *k, *vt, *ao, *uc;
    cudaGetSymbolAddress((void**)&q,  g_q);
    cudaGetSymbolAddress((void**)&k,  g_k);
    cudaGetSymbolAddress((void**)&vt, g_v);
    cudaGetSymbolAddress((void**)&ao, g_ao);
    cudaGetSymbolAddress((void**)&uc, g_uc);

    cudaFuncSetAttribute(attn_tc, cudaFuncAttributeMaxDynamicSharedMemorySize, ATT_SMEM);

    // per-query uncertainty mean
    uc_kernel<<<(MTOT*32 + 255)/256, 256>>>(x_u);

    // projections (tensor cores, tf32): q folded with SCALE*uc; V written transposed
    dim3 ggrid(CC/128, MTOT/128);    // (6, 64)
    gemm_tc<<<ggrid, 256>>>(x_q, Wq, q,  uc,      SCALE_Q, nullptr, 0);
    gemm_tc<<<ggrid, 256>>>(x_k, Wk, k,  nullptr, 1.0f,    nullptr, 0);
    gemm_tc<<<ggrid, 256>>>(x_v, Wv, vt, nullptr, 1.0f,    nullptr, 1);

    // flash attention (tf32 tensor cores)
    dim3 agrid(NN/64, HH, BB);       // (32, 12, 4)
    attn_tc<<<agrid, 128, ATT_SMEM>>>(q, k, vt, ao);

    // output projection + bias
    gemm_tc<<<ggrid, 256>>>(ao, Wp, out, nullptr, 1.0f, bp, 0);
}

// round 7
// speedup vs baseline: 3.1670x; 1.1570x over previous
#include <cuda_runtime.h>
#include <cuda_bf16.h>
#include <cstdint>

#define BB 4
#define NN 2048
#define CC 768
#define HH 12
#define DD 64
#define MTOT (BB*NN)          /* 8192 */
#define SCALE_Q 0.125f        /* 64^-0.5 */

// ---------------- scratch (no allocation allowed) ----------------
__device__ float g_q [MTOT*CC];
__device__ float g_k [MTOT*CC];
__device__ float g_v [MTOT*CC];   // holds V TRANSPOSED: [B][H][D][N]
__device__ float g_ao[MTOT*CC];
__device__ float g_uc[MTOT];

// ---------------- helpers ----------------
__device__ __forceinline__ uint32_t smem_u32(const void* p) {
    uint32_t a;
    asm("{ .reg .u64 t; cvta.to.shared.u64 t, %1; cvt.u32.u64 %0, t; }" : "=r"(a) : "l"(p));
    return a;
}
__device__ __forceinline__ uint32_t f2tf(float f) {
    uint32_t r;
    asm("cvt.rna.tf32.f32 %0, %1;" : "=r"(r) : "f"(f));
    return r;
}
__device__ __forceinline__ void mma_tf32(float* d, const uint32_t* a, const uint32_t* b, const float* c) {
    asm volatile("mma.sync.aligned.m16n8k8.row.col.f32.tf32.tf32.f32 "
        "{%0,%1,%2,%3}, {%4,%5,%6,%7}, {%8,%9}, {%10,%11,%12,%13};\n"
        : "=f"(d[0]), "=f"(d[1]), "=f"(d[2]), "=f"(d[3])
        : "r"(a[0]), "r"(a[1]), "r"(a[2]), "r"(a[3]),
          "r"(b[0]), "r"(b[1]),
          "f"(c[0]), "f"(c[1]), "f"(c[2]), "f"(c[3]));
}
// ldmatrix x4: loads 4 8x8-b16 matrices (= 4 tf32 8x4-word tiles)
__device__ __forceinline__ void ldsm_x4(uint32_t* r, uint32_t saddr) {
    asm volatile("ldmatrix.sync.aligned.m8n8.x4.shared.b16 {%0,%1,%2,%3}, [%4];"
        : "=r"(r[0]), "=r"(r[1]), "=r"(r[2]), "=r"(r[3]) : "r"(saddr));
}

// A-frag lane offset (in floats) for row-major [row][k] tile, stride S:
//   M0: rows +0..7, k+0..3 | M1: rows +8..15, k+0..3 | M2: rows +0..7, k+4..7 | M3: rows +8..15, k+4..7
#define AOFF(lane, S) ((((lane)&7) + (((lane)>>3)&1)*8)*(S) + (((lane)>>4)&1)*4)
// B-frag pair lane offset: M0: n+0..7,k0 | M1: n+0..7,k0+4 | M2: n+8..15,k0 | M3: n+8..15,k0+4
#define BOFF(lane, S) ((((lane)&7) + (((lane)>>4)&1)*8)*(S) + (((lane)>>3)&1)*4)

// ---------------- uc = mean(x_u, axis=-1), one warp per row ----------------
__global__ void uc_kernel(const float* __restrict__ xu)
{
    int gid  = blockIdx.x * blockDim.x + threadIdx.x;
    int row  = gid >> 5;
    int lane = gid & 31;
    if (row >= MTOT) return;
    const float* p = xu + (size_t)row * CC;
    float s = 0.f;
    #pragma unroll
    for (int i = 0; i < CC/32; i++) s += p[lane + 32*i];
    #pragma unroll
    for (int off = 16; off; off >>= 1) s += __shfl_down_sync(0xffffffffu, s, off);
    if (lane == 0) g_uc[row] = s * (1.0f / (float)CC);
}

// ================= tf32 mma GEMM: Y = X @ W^T =================
// BM=128, BN=128, BK=16. 256 threads = 8 warps (2m x 4n); warp tile 64x32.
// vtMode: write as V^T [B][H][D][N]. cvtOut: round outputs to tf32 (for q/k/v).
#define GSTRIDE 20
__global__ __launch_bounds__(256)
void gemm_tc(const float* __restrict__ X, const float* __restrict__ W,
             float* __restrict__ Y,
             const float* __restrict__ rowScale, float scaleConst,
             const float* __restrict__ bias, int vtMode, int cvtOut)
{
    __shared__ __align__(16) uint32_t As[2][128][GSTRIDE];
    __shared__ __align__(16) uint32_t Bs[2][128][GSTRIDE];

    const int tid = threadIdx.x;
    const int wid = tid >> 5;
    const int lane = tid & 31;
    const int lq = lane >> 2;
    const int lc = lane & 3;
    const int wm = wid >> 2;      // 0..1
    const int wn = wid & 3;       // 0..3
    const int m0 = blockIdx.y * 128;
    const int n0 = blockIdx.x * 128;

    const uint32_t sbA = smem_u32(As);
    const uint32_t sbB = smem_u32(Bs);
    const uint32_t aoff = AOFF(lane, GSTRIDE);
    const uint32_t boff = BOFF(lane, GSTRIDE);

    const int cr = tid >> 2;          // 0..63
    const int cf = (tid & 3) * 4;     // 0,4,8,12
    const float* pA = X + (size_t)(m0 + cr) * CC + cf;
    const float* pB = W + (size_t)(n0 + cr) * CC + cf;

    float acc[4][4][4];
    #pragma unroll
    for (int i = 0; i < 4; i++)
        #pragma unroll
        for (int j = 0; j < 4; j++)
            #pragma unroll
            for (int t = 0; t < 4; t++) acc[i][j][t] = 0.f;

    float4 rA0 = *(const float4*)(pA);
    float4 rA1 = *(const float4*)(pA + (size_t)64 * CC);
    float4 rB0 = *(const float4*)(pB);
    float4 rB1 = *(const float4*)(pB + (size_t)64 * CC);
    As[0][cr   ][cf+0]=f2tf(rA0.x); As[0][cr   ][cf+1]=f2tf(rA0.y); As[0][cr   ][cf+2]=f2tf(rA0.z); As[0][cr   ][cf+3]=f2tf(rA0.w);
    As[0][cr+64][cf+0]=f2tf(rA1.x); As[0][cr+64][cf+1]=f2tf(rA1.y); As[0][cr+64][cf+2]=f2tf(rA1.z); As[0][cr+64][cf+3]=f2tf(rA1.w);
    Bs[0][cr   ][cf+0]=f2tf(rB0.x); Bs[0][cr   ][cf+1]=f2tf(rB0.y); Bs[0][cr   ][cf+2]=f2tf(rB0.z); Bs[0][cr   ][cf+3]=f2tf(rB0.w);
    Bs[0][cr+64][cf+0]=f2tf(rB1.x); Bs[0][cr+64][cf+1]=f2tf(rB1.y); Bs[0][cr+64][cf+2]=f2tf(rB1.z); Bs[0][cr+64][cf+3]=f2tf(rB1.w);
    __syncthreads();

    const int NSTAGE = CC / 16;   // 48
    #pragma unroll 1
    for (int s = 0; s < NSTAGE; s++) {
        int cur = s & 1;
        if (s + 1 < NSTAGE) {
            int ko = (s + 1) * 16;
            rA0 = *(const float4*)(pA + ko);
            rA1 = *(const float4*)(pA + (size_t)64 * CC + ko);
            rB0 = *(const float4*)(pB + ko);
            rB1 = *(const float4*)(pB + (size_t)64 * CC + ko);
        }
        const uint32_t baseA = sbA + 4u*(cur*128*GSTRIDE + wm*64*GSTRIDE + aoff);
        const uint32_t baseB = sbB + 4u*(cur*128*GSTRIDE + wn*32*GSTRIDE + boff);
        #pragma unroll
        for (int kk = 0; kk < 2; kk++) {
            const int k0 = kk * 8;
            uint32_t af[4][4];
            #pragma unroll
            for (int mi = 0; mi < 4; mi++)
                ldsm_x4(af[mi], baseA + 4u*(mi*16*GSTRIDE + k0));
            uint32_t bf[2][4];
            #pragma unroll
            for (int p = 0; p < 2; p++)
                ldsm_x4(bf[p], baseB + 4u*(p*16*GSTRIDE + k0));
            #pragma unroll
            for (int nj = 0; nj < 4; nj++)
                #pragma unroll
                for (int mi = 0; mi < 4; mi++)
                    mma_tf32(acc[mi][nj], af[mi], &bf[nj>>1][(nj&1)*2], acc[mi][nj]);
        }
        if (s + 1 < NSTAGE) {
            int nxt = 1 - cur;
            As[nxt][cr   ][cf+0]=f2tf(rA0.x); As[nxt][cr   ][cf+1]=f2tf(rA0.y); As[nxt][cr   ][cf+2]=f2tf(rA0.z); As[nxt][cr   ][cf+3]=f2tf(rA0.w);
            As[nxt][cr+64][cf+0]=f2tf(rA1.x); As[nxt][cr+64][cf+1]=f2tf(rA1.y); As[nxt][cr+64][cf+2]=f2tf(rA1.z); As[nxt][cr+64][cf+3]=f2tf(rA1.w);
            Bs[nxt][cr   ][cf+0]=f2tf(rB0.x); Bs[nxt][cr   ][cf+1]=f2tf(rB0.y); Bs[nxt][cr   ][cf+2]=f2tf(rB0.z); Bs[nxt][cr   ][cf+3]=f2tf(rB0.w);
            Bs[nxt][cr+64][cf+0]=f2tf(rB1.x); Bs[nxt][cr+64][cf+1]=f2tf(rB1.y); Bs[nxt][cr+64][cf+2]=f2tf(rB1.z); Bs[nxt][cr+64][cf+3]=f2tf(rB1.w);
        }
        __syncthreads();
    }

    // epilogue
    #pragma unroll
    for (int mi = 0; mi < 4; mi++) {
        int row0 = m0 + wm*64 + mi*16 + lq;
        int row1 = row0 + 8;
        float rs0 = scaleConst, rs1 = scaleConst;
        if (rowScale) { rs0 *= rowScale[row0]; rs1 *= rowScale[row1]; }
        #pragma unroll
        for (int nj = 0; nj < 4; nj++) {
            int col = n0 + wn*32 + nj*8 + 2*lc;
            float v0 = acc[mi][nj][0]*rs0, v1 = acc[mi][nj][1]*rs0;
            float v2 = acc[mi][nj][2]*rs1, v3 = acc[mi][nj][3]*rs1;
            if (cvtOut) {
                v0 = __uint_as_float(f2tf(v0)); v1 = __uint_as_float(f2tf(v1));
                v2 = __uint_as_float(f2tf(v2)); v3 = __uint_as_float(f2tf(v3));
            }
            if (!vtMode) {
                if (bias) { float b0 = bias[col], b1 = bias[col+1]; v0 += b0; v1 += b1; v2 += b0; v3 += b1; }
                *(float2*)(Y + (size_t)row0 * CC + col) = make_float2(v0, v1);
                *(float2*)(Y + (size_t)row1 * CC + col) = make_float2(v2, v3);
            } else {
                int h = col >> 6, d = col & 63;
                int b0i = row0 >> 11, n0i = row0 & 2047;
                int b1i = row1 >> 11, n1i = row1 & 2047;
                float* base0 = Y + ((size_t)(b0i*HH + h)*DD) * NN;
                float* base1 = Y + ((size_t)(b1i*HH + h)*DD) * NN;
                base0[(size_t)d*NN + n0i]     = v0;
                base0[(size_t)(d+1)*NN + n0i] = v1;
                base1[(size_t)d*NN + n1i]     = v2;
                base1[(size_t)(d+1)*NN + n1i] = v3;
            }
        }
    }
}

// ================= flash attention, tf32 mma + ldmatrix =================
// grid (NN/64, HH, BB), 128 threads = 4 warps, each warp owns 16 q rows.
// Q/K (pre-rounded tf32) [B*N][C]; Vt (pre-rounded) [B][H][D][N]; O fp32 [B*N][C].
#define ASTRIDE 68
#define ATT_SMEM (4*64*ASTRIDE*4)
__global__ __launch_bounds__(128)
void attn_tc(const float* __restrict__ Q, const float* __restrict__ K,
             const float* __restrict__ Vt, float* __restrict__ O)
{
    extern __shared__ uint32_t sm[];
    uint32_t* Qs = sm;                      // [64][68]  (q, d)
    uint32_t* Ks = sm + 64*ASTRIDE;         // [64][68]  (key, d)
    uint32_t* Vs = sm + 2*64*ASTRIDE;       // [64][68]  (d, key)
    uint32_t* Ps = sm + 3*64*ASTRIDE;       // [64][68]  (q, key)

    const int tid  = threadIdx.x;
    const int wid  = tid >> 5;
    const int lane = tid & 31;
    const int lc   = lane & 3;
    const int wq   = wid * 16;
    const int b    = blockIdx.z;
    const int h    = blockIdx.y;
    const int n0q  = blockIdx.x * 64;

    const uint32_t sbQ = smem_u32(Qs);
    const uint32_t sbK = smem_u32(Ks);
    const uint32_t sbV = smem_u32(Vs);
    const uint32_t sbP = smem_u32(Ps);
    const uint32_t aoff = AOFF(lane, ASTRIDE);
    const uint32_t boff = BOFF(lane, ASTRIDE);

    const float* Qb  = Q + ((size_t)(b*NN + n0q)) * CC + h * DD;
    const float* Kb  = K + ((size_t)b * NN) * CC + h * DD;
    const float* Vtb = Vt + ((size_t)(b*HH + h) * DD) * NN;

    // load Q tile (already tf32-rounded): straight float4 copy
    {
        const int row = tid >> 4;
        const int f4  = (tid & 15) * 4;
        #pragma unroll
        for (int i = 0; i < 4; i++) {
            int r = row + i*8;
            *(float4*)&Qs[r*ASTRIDE + f4]      = *(const float4*)(Qb + (size_t)r * CC + f4);
            *(float4*)&Qs[(r+32)*ASTRIDE + f4] = *(const float4*)(Qb + (size_t)(r+32) * CC + f4);
        }
    }

    float oacc[8][4];
    #pragma unroll
    for (int i = 0; i < 8; i++)
        #pragma unroll
        for (int t = 0; t < 4; t++) oacc[i][t] = 0.f;
    float mrow0 = -1e30f, mrow1 = -1e30f, lrow0 = 0.f, lrow1 = 0.f;

    #pragma unroll 1
    for (int kb = 0; kb < NN/64; kb++) {
        // ---- stage K (key,d) and V (d,key) tiles: plain float4 copies ----
        {
            const int row = tid >> 4;
            const int f4  = (tid & 15) * 4;
            const float* ksrc = Kb + (size_t)(kb*64) * CC;
            const float* vsrc = Vtb + kb*64;
            #pragma unroll
            for (int i = 0; i < 8; i++) {
                int r = row + i*8;
                *(float4*)&Ks[r*ASTRIDE + f4] = *(const float4*)(ksrc + (size_t)r * CC + f4);
                *(float4*)&Vs[r*ASTRIDE + f4] = *(const float4*)(vsrc + (size_t)r * NN + f4);
            }
        }
        __syncthreads();

        // ---- S = Q K^T ----
        float sacc[8][4];
        #pragma unroll
        for (int i = 0; i < 8; i++)
            #pragma unroll
            for (int t = 0; t < 4; t++) sacc[i][t] = 0.f;
        #pragma unroll
        for (int ks = 0; ks < 8; ks++) {
            const int k0 = ks * 8;
            uint32_t af[4];
            ldsm_x4(af, sbQ + 4u*(wq*ASTRIDE + k0 + aoff));
            #pragma unroll
            for (int p = 0; p < 4; p++) {
                uint32_t bf[4];
                ldsm_x4(bf, sbK + 4u*(p*16*ASTRIDE + k0 + boff));
                mma_tf32(sacc[2*p],   af, bf,   sacc[2*p]);
                mma_tf32(sacc[2*p+1], af, bf+2, sacc[2*p+1]);
            }
        }

        // ---- online softmax (register-resident; quad shuffles) ----
        float rmax0 = -1e30f, rmax1 = -1e30f;
        #pragma unroll
        for (int nt = 0; nt < 8; nt++) {
            rmax0 = fmaxf(rmax0, fmaxf(sacc[nt][0], sacc[nt][1]));
            rmax1 = fmaxf(rmax1, fmaxf(sacc[nt][2], sacc[nt][3]));
        }
        rmax0 = fmaxf(rmax0, __shfl_xor_sync(0xffffffffu, rmax0, 1));
        rmax0 = fmaxf(rmax0, __shfl_xor_sync(0xffffffffu, rmax0, 2));
        rmax1 = fmaxf(rmax1, __shfl_xor_sync(0xffffffffu, rmax1, 1));
        rmax1 = fmaxf(rmax1, __shfl_xor_sync(0xffffffffu, rmax1, 2));
        float nm0 = fmaxf(mrow0, rmax0);
        float nm1 = fmaxf(mrow1, rmax1);
        float al0 = __expf(mrow0 - nm0);
        float al1 = __expf(mrow1 - nm1);
        float sum0 = 0.f, sum1 = 0.f;
        const int lqr = lane >> 2;
        #pragma unroll
        for (int nt = 0; nt < 8; nt++) {
            float p0 = __expf(sacc[nt][0] - nm0);
            float p1 = __expf(sacc[nt][1] - nm0);
            float p2 = __expf(sacc[nt][2] - nm1);
            float p3 = __expf(sacc[nt][3] - nm1);
            sum0 += p0 + p1; sum1 += p2 + p3;
            *(uint2*)&Ps[(wq + lqr    )*ASTRIDE + nt*8 + 2*lc] = make_uint2(f2tf(p0), f2tf(p1));
            *(uint2*)&Ps[(wq + lqr + 8)*ASTRIDE + nt*8 + 2*lc] = make_uint2(f2tf(p2), f2tf(p3));
        }
        sum0 += __shfl_xor_sync(0xffffffffu, sum0, 1);
        sum0 += __shfl_xor_sync(0xffffffffu, sum0, 2);
        sum1 += __shfl_xor_sync(0xffffffffu, sum1, 1);
        sum1 += __shfl_xor_sync(0xffffffffu, sum1, 2);
        lrow0 = lrow0 * al0 + sum0;  mrow0 = nm0;
        lrow1 = lrow1 * al1 + sum1;  mrow1 = nm1;
        #pragma unroll
        for (int nt = 0; nt < 8; nt++) {
            oacc[nt][0] *= al0; oacc[nt][1] *= al0;
            oacc[nt][2] *= al1; oacc[nt][3] *= al1;
        }
        __syncwarp();

        // ---- O += P @ V : contraction over 64 keys ----
        #pragma unroll
        for (int ks = 0; ks < 8; ks++) {
            const int k0 = ks * 8;
            uint32_t af[4];
            ldsm_x4(af, sbP + 4u*(wq*ASTRIDE + k0 + aoff));
            #pragma unroll
            for (int p = 0; p < 4; p++) {
                uint32_t bf[4];
                ldsm_x4(bf, sbV + 4u*(p*16*ASTRIDE + k0 + boff));
                mma_tf32(oacc[2*p],   af, bf,   oacc[2*p]);
                mma_tf32(oacc[2*p+1], af, bf+2, oacc[2*p+1]);
            }
        }
        __syncthreads();
    }

    // ---- normalize and write ----
    const int lqr = lane >> 2;
    float li0 = 1.0f / lrow0;
    float li1 = 1.0f / lrow1;
    float* dst0 = O + ((size_t)(b*NN + n0q + wq + lqr    )) * CC + h * DD;
    float* dst1 = O + ((size_t)(b*NN + n0q + wq + lqr + 8)) * CC + h * DD;
    #pragma unroll
    for (int nt = 0; nt < 8; nt++) {
        *(float2*)(dst0 + nt*8 + 2*lc) = make_float2(oacc[nt][0]*li0, oacc[nt][1]*li0);
        *(float2*)(dst1 + nt*8 + 2*lc) = make_float2(oacc[nt][2]*li1, oacc[nt][3]*li1);
    }
}

// ---------------- launch ----------------
extern "C" void kernel_launch(void* const* d_in, const int* in_sizes, int n_in,
                              void* d_out, int out_size)
{
    const float* x_q = (const float*)d_in[0];
    const float* x_k = (const float*)d_in[1];
    const float* x_v = (const float*)d_in[2];
    const float* x_u = (const float*)d_in[3];
    const float* Wq  = (const float*)d_in[4];
    const float* Wk  = (const float*)d_in[5];
    const float* Wv  = (const float*)d_in[6];
    const float* Wp  = (const float*)d_in[7];
    const float* bp  = (const float*)d_in[8];
    float* out = (float*)d_out;

    float *q, *k, *vt, *ao, *uc;
    cudaGetSymbolAddress((void**)&q,  g_q);
    cudaGetSymbolAddress((void**)&k,  g_k);
    cudaGetSymbolAddress((void**)&vt, g_v);
    cudaGetSymbolAddress((void**)&ao, g_ao);
    cudaGetSymbolAddress((void**)&uc, g_uc);

    cudaFuncSetAttribute(attn_tc, cudaFuncAttributeMaxDynamicSharedMemorySize, ATT_SMEM);

    // per-query uncertainty mean
    uc_kernel<<<(MTOT*32 + 255)/256, 256>>>(x_u);

    // projections (tf32 tensor cores); q folded with SCALE*uc.
    // Q/K/V outputs pre-rounded to tf32 so the attention kernel needs no cvt.
    dim3 ggrid(CC/128, MTOT/128);    // (6, 64)
    gemm_tc<<<ggrid, 256>>>(x_q, Wq, q,  uc,      SCALE_Q, nullptr, 0, 1);
    gemm_tc<<<ggrid, 256>>>(x_k, Wk, k,  nullptr, 1.0f,    nullptr, 0, 1);
    gemm_tc<<<ggrid, 256>>>(x_v, Wv, vt, nullptr, 1.0f,    nullptr, 1, 1);

    // flash attention (tf32 tensor cores + ldmatrix)
    dim3 agrid(NN/64, HH, BB);       // (32, 12, 4)
    attn_tc<<<agrid, 128, ATT_SMEM>>>(q, k, vt, ao);

    // output projection + bias (full fp32 output)
    gemm_tc<<<ggrid, 256>>>(ao, Wp, out, nullptr, 1.0f, bp, 0, 0);
}

// round 8
// speedup vs baseline: 3.7125x; 1.1722x over previous
#include <cuda_runtime.h>
#include <cstdint>

#define BB 4
#define NN 2048
#define CC 768
#define HH 12
#define DD 64
#define MTOT (BB*NN)          /* 8192 */
#define SCALE_Q 0.125f        /* 64^-0.5 */

// ---------------- scratch (no allocation allowed) ----------------
__device__ float g_q [MTOT*CC];
__device__ float g_k [MTOT*CC];
__device__ float g_v [MTOT*CC];   // V TRANSPOSED: [B][H][D][N]
__device__ float g_ao[MTOT*CC];
__device__ float g_uc[MTOT];
__device__ float g_xq[MTOT*CC];   // tf32-rounded inputs
__device__ float g_xk[MTOT*CC];
__device__ float g_xv[MTOT*CC];
__device__ float g_wq[CC*CC];     // tf32-rounded weights
__device__ float g_wk[CC*CC];
__device__ float g_wv[CC*CC];
__device__ float g_wp[CC*CC];

// ---------------- helpers ----------------
__device__ __forceinline__ uint32_t smem_u32(const void* p) {
    uint32_t a;
    asm("{ .reg .u64 t; cvta.to.shared.u64 t, %1; cvt.u32.u64 %0, t; }" : "=r"(a) : "l"(p));
    return a;
}
__device__ __forceinline__ uint32_t f2tf(float f) {
    uint32_t r;
    asm("cvt.rna.tf32.f32 %0, %1;" : "=r"(r) : "f"(f));
    return r;
}
__device__ __forceinline__ void mma_tf32(float* d, const uint32_t* a, const uint32_t* b, const float* c) {
    asm volatile("mma.sync.aligned.m16n8k8.row.col.f32.tf32.tf32.f32 "
        "{%0,%1,%2,%3}, {%4,%5,%6,%7}, {%8,%9}, {%10,%11,%12,%13};\n"
        : "=f"(d[0]), "=f"(d[1]), "=f"(d[2]), "=f"(d[3])
        : "r"(a[0]), "r"(a[1]), "r"(a[2]), "r"(a[3]),
          "r"(b[0]), "r"(b[1]),
          "f"(c[0]), "f"(c[1]), "f"(c[2]), "f"(c[3]));
}
__device__ __forceinline__ void ldsm_x4(uint32_t* r, uint32_t saddr) {
    asm volatile("ldmatrix.sync.aligned.m8n8.x4.shared.b16 {%0,%1,%2,%3}, [%4];"
        : "=r"(r[0]), "=r"(r[1]), "=r"(r[2]), "=r"(r[3]) : "r"(saddr));
}
__device__ __forceinline__ void cpasync16(uint32_t dst, const void* src) {
    asm volatile("cp.async.cg.shared.global [%0], [%1], 16;" :: "r"(dst), "l"(src));
}
#define CP_COMMIT() asm volatile("cp.async.commit_group;" ::: "memory")
#define CP_WAIT(n)  asm volatile("cp.async.wait_group %0;" :: "n"(n) : "memory")

// fragment lane offsets (floats), stride S
#define AOFF(lane, S) ((((lane)&7) + (((lane)>>3)&1)*8)*(S) + (((lane)>>4)&1)*4)
#define BOFF(lane, S) ((((lane)&7) + (((lane)>>4)&1)*8)*(S) + (((lane)>>3)&1)*4)

// ---------------- tf32 pre-round (elementwise) ----------------
__global__ void cvt_tf32(const float* __restrict__ src, float* __restrict__ dst, int n4)
{
    int i = blockIdx.x * blockDim.x + threadIdx.x;
    if (i < n4) {
        float4 v = *(const float4*)(src + (size_t)i*4);
        uint4 o;
        o.x = f2tf(v.x); o.y = f2tf(v.y); o.z = f2tf(v.z); o.w = f2tf(v.w);
        *(uint4*)(dst + (size_t)i*4) = o;
    }
}

// ---------------- uc = mean(x_u, axis=-1), one warp per row ----------------
__global__ void uc_kernel(const float* __restrict__ xu)
{
    int gid  = blockIdx.x * blockDim.x + threadIdx.x;
    int row  = gid >> 5;
    int lane = gid & 31;
    if (row >= MTOT) return;
    const float* p = xu + (size_t)row * CC;
    float s = 0.f;
    #pragma unroll
    for (int i = 0; i < CC/32; i++) s += p[lane + 32*i];
    #pragma unroll
    for (int off = 16; off; off >>= 1) s += __shfl_down_sync(0xffffffffu, s, off);
    if (lane == 0) g_uc[row] = s * (1.0f / (float)CC);
}

// ================= tf32 mma GEMM: Y = X @ W^T (operands pre-rounded) =================
// BM=128, BN=128, BK=32, cp.async double-buffered. 8 warps (2m x 4n), warp tile 64x32.
#define GST 36
#define GEMM_SMEM (4*128*GST*4)   /* 2 bufs x (A+B) x 128x36 words = 73728 B */
__global__ __launch_bounds__(256, 2)
void gemm_tc(const float* __restrict__ X, const float* __restrict__ W,
             float* __restrict__ Y,
             const float* __restrict__ rowScale, float scaleConst,
             const float* __restrict__ bias, int vtMode, int cvtOut)
{
    extern __shared__ uint32_t gsm[];
    const int tid = threadIdx.x;
    const int wid = tid >> 5;
    const int lane = tid & 31;
    const int lq = lane >> 2;
    const int lc = lane & 3;
    const int wm = wid >> 2;      // 0..1
    const int wn = wid & 3;       // 0..3
    const int m0 = blockIdx.y * 128;
    const int n0 = blockIdx.x * 128;

    const uint32_t sbA = smem_u32(gsm);
    const uint32_t sbB = sbA + 4u*2*128*GST;
    const uint32_t aoff = AOFF(lane, GST);
    const uint32_t boff = BOFF(lane, GST);

    float acc[4][4][4];
    #pragma unroll
    for (int i = 0; i < 4; i++)
        #pragma unroll
        for (int j = 0; j < 4; j++)
            #pragma unroll
            for (int t = 0; t < 4; t++) acc[i][j][t] = 0.f;

    auto issue = [&](int s, int buf) {
        const int k0 = s * 32;
        #pragma unroll
        for (int i = 0; i < 4; i++) {
            int lin = tid + 256*i;          // 0..1023
            int row = lin >> 3, f4 = lin & 7;
            cpasync16(sbA + 4u*(buf*128*GST + row*GST + f4*4),
                      X + (size_t)(m0+row)*CC + k0 + f4*4);
            cpasync16(sbB + 4u*(buf*128*GST + row*GST + f4*4),
                      W + (size_t)(n0+row)*CC + k0 + f4*4);
        }
        CP_COMMIT();
    };

    const int NSTAGE = CC / 32;   // 24
    issue(0, 0);
    #pragma unroll 1
    for (int s = 0; s < NSTAGE; s++) {
        const int cur = s & 1;
        if (s + 1 < NSTAGE) { issue(s + 1, cur ^ 1); CP_WAIT(1); }
        else                { CP_WAIT(0); }
        __syncthreads();
        const uint32_t baseA = sbA + 4u*(cur*128*GST + wm*64*GST + aoff);
        const uint32_t baseB = sbB + 4u*(cur*128*GST + wn*32*GST + boff);
        #pragma unroll
        for (int kk = 0; kk < 4; kk++) {
            const int k0 = kk * 8;
            uint32_t af[4][4];
            #pragma unroll
            for (int mi = 0; mi < 4; mi++)
                ldsm_x4(af[mi], baseA + 4u*(mi*16*GST + k0));
            uint32_t bf[2][4];
            #pragma unroll
            for (int p = 0; p < 2; p++)
                ldsm_x4(bf[p], baseB + 4u*(p*16*GST + k0));
            #pragma unroll
            for (int nj = 0; nj < 4; nj++)
                #pragma unroll
                for (int mi = 0; mi < 4; mi++)
                    mma_tf32(acc[mi][nj], af[mi], &bf[nj>>1][(nj&1)*2], acc[mi][nj]);
        }
        __syncthreads();
    }

    // epilogue
    #pragma unroll
    for (int mi = 0; mi < 4; mi++) {
        int row0 = m0 + wm*64 + mi*16 + lq;
        int row1 = row0 + 8;
        float rs0 = scaleConst, rs1 = scaleConst;
        if (rowScale) { rs0 *= rowScale[row0]; rs1 *= rowScale[row1]; }
        #pragma unroll
        for (int nj = 0; nj < 4; nj++) {
            int col = n0 + wn*32 + nj*8 + 2*lc;
            float v0 = acc[mi][nj][0]*rs0, v1 = acc[mi][nj][1]*rs0;
            float v2 = acc[mi][nj][2]*rs1, v3 = acc[mi][nj][3]*rs1;
            if (cvtOut) {
                v0 = __uint_as_float(f2tf(v0)); v1 = __uint_as_float(f2tf(v1));
                v2 = __uint_as_float(f2tf(v2)); v3 = __uint_as_float(f2tf(v3));
            }
            if (!vtMode) {
                if (bias) { float b0 = bias[col], b1 = bias[col+1]; v0 += b0; v1 += b1; v2 += b0; v3 += b1; }
                *(float2*)(Y + (size_t)row0 * CC + col) = make_float2(v0, v1);
                *(float2*)(Y + (size_t)row1 * CC + col) = make_float2(v2, v3);
            } else {
                int h = col >> 6, d = col & 63;
                int b0i = row0 >> 11, n0i = row0 & 2047;
                int b1i = row1 >> 11, n1i = row1 & 2047;
                float* base0 = Y + ((size_t)(b0i*HH + h)*DD) * NN;
                float* base1 = Y + ((size_t)(b1i*HH + h)*DD) * NN;
                base0[(size_t)d*NN + n0i]     = v0;
                base0[(size_t)(d+1)*NN + n0i] = v1;
                base1[(size_t)d*NN + n1i]     = v2;
                base1[(size_t)(d+1)*NN + n1i] = v3;
            }
        }
    }
}

// ================= flash attention: 128q/CTA, Q in regs, cp.async KV prefetch =================
// grid (NN/128, HH, BB), 256 threads = 8 warps, each warp 16 q rows.
#define AST 68
// smem words: K[2][64][AST] | V[2][64][AST] | P[128][AST]  (P doubles as Q staging)
#define ATT_SMEM ((4*64*AST + 128*AST)*4)   /* 104448 B */
__global__ __launch_bounds__(256, 2)
void attn_tc(const float* __restrict__ Q, const float* __restrict__ K,
             const float* __restrict__ Vt, float* __restrict__ O)
{
    extern __shared__ uint32_t smw[];
    const int tid  = threadIdx.x;
    const int wid  = tid >> 5;
    const int lane = tid & 31;
    const int lc   = lane & 3;
    const int lqr  = lane >> 2;
    const int wq   = wid * 16;
    const int b    = blockIdx.z;
    const int h    = blockIdx.y;
    const int n0q  = blockIdx.x * 128;

    const uint32_t sbK = smem_u32(smw);
    const uint32_t sbV = sbK + 4u*2*64*AST;
    const uint32_t sbP = sbK + 4u*4*64*AST;
    uint32_t* Ps = smw + 4*64*AST;
    const uint32_t aoff = AOFF(lane, AST);
    const uint32_t boff = BOFF(lane, AST);

    const float* Qb  = Q + ((size_t)(b*NN + n0q)) * CC + h * DD;
    const float* Kb  = K + ((size_t)b * NN) * CC + h * DD;
    const float* Vtb = Vt + ((size_t)(b*HH + h) * DD) * NN;

    // stage Q (128x64) into P buffer
    #pragma unroll
    for (int i = 0; i < 8; i++) {
        int lin = tid + 256*i;          // 0..2047
        int row = lin >> 4, f4 = lin & 15;
        cpasync16(sbP + 4u*(row*AST + f4*4), Qb + (size_t)row*CC + f4*4);
    }
    CP_COMMIT();

    auto issueKV = [&](int kb, int buf) {
        #pragma unroll
        for (int i = 0; i < 4; i++) {
            int lin = tid + 256*i;      // 0..1023
            int row = lin >> 4, f4 = lin & 15;
            cpasync16(sbK + 4u*(buf*64*AST + row*AST + f4*4),
                      Kb + (size_t)(kb*64 + row)*CC + f4*4);
            cpasync16(sbV + 4u*(buf*64*AST + row*AST + f4*4),
                      Vtb + (size_t)row*NN + kb*64 + f4*4);
        }
        CP_COMMIT();
    };

    issueKV(0, 0);
    CP_WAIT(1);            // Q staged (KV0 still in flight)
    __syncthreads();

    // Q fragments -> registers (rows wq..wq+15 are warp-private)
    uint32_t qf[8][4];
    #pragma unroll
    for (int ks = 0; ks < 8; ks++)
        ldsm_x4(qf[ks], sbP + 4u*(wq*AST + ks*8 + aoff));

    float oacc[8][4];
    #pragma unroll
    for (int i = 0; i < 8; i++)
        #pragma unroll
        for (int t = 0; t < 4; t++) oacc[i][t] = 0.f;
    float mrow0 = -1e30f, mrow1 = -1e30f, lrow0 = 0.f, lrow1 = 0.f;

    #pragma unroll 1
    for (int kb = 0; kb < NN/64; kb++) {
        const int cur = kb & 1;
        if (kb + 1 < NN/64) { issueKV(kb + 1, cur ^ 1); CP_WAIT(1); }
        else                { CP_WAIT(0); }
        __syncthreads();
        const uint32_t bK = sbK + 4u*(cur*64*AST);
        const uint32_t bV = sbV + 4u*(cur*64*AST);

        // ---- S = Q K^T ----
        float sacc[8][4];
        #pragma unroll
        for (int i = 0; i < 8; i++)
            #pragma unroll
            for (int t = 0; t < 4; t++) sacc[i][t] = 0.f;
        #pragma unroll
        for (int ks = 0; ks < 8; ks++) {
            const int k0 = ks * 8;
            #pragma unroll
            for (int p = 0; p < 4; p++) {
                uint32_t bf[4];
                ldsm_x4(bf, bK + 4u*(p*16*AST + k0 + boff));
                mma_tf32(sacc[2*p],   qf[ks], bf,   sacc[2*p]);
                mma_tf32(sacc[2*p+1], qf[ks], bf+2, sacc[2*p+1]);
            }
        }

        // ---- online softmax ----
        float rmax0 = -1e30f, rmax1 = -1e30f;
        #pragma unroll
        for (int nt = 0; nt < 8; nt++) {
            rmax0 = fmaxf(rmax0, fmaxf(sacc[nt][0], sacc[nt][1]));
            rmax1 = fmaxf(rmax1, fmaxf(sacc[nt][2], sacc[nt][3]));
        }
        rmax0 = fmaxf(rmax0, __shfl_xor_sync(0xffffffffu, rmax0, 1));
        rmax0 = fmaxf(rmax0, __shfl_xor_sync(0xffffffffu, rmax0, 2));
        rmax1 = fmaxf(rmax1, __shfl_xor_sync(0xffffffffu, rmax1, 1));
        rmax1 = fmaxf(rmax1, __shfl_xor_sync(0xffffffffu, rmax1, 2));
        float nm0 = fmaxf(mrow0, rmax0);
        float nm1 = fmaxf(mrow1, rmax1);
        float al0 = __expf(mrow0 - nm0);
        float al1 = __expf(mrow1 - nm1);
        float sum0 = 0.f, sum1 = 0.f;
        #pragma unroll
        for (int nt = 0; nt < 8; nt++) {
            float p0 = __expf(sacc[nt][0] - nm0);
            float p1 = __expf(sacc[nt][1] - nm0);
            float p2 = __expf(sacc[nt][2] - nm1);
            float p3 = __expf(sacc[nt][3] - nm1);
            sum0 += p0 + p1; sum1 += p2 + p3;
            *(uint2*)&Ps[(wq + lqr    )*AST + nt*8 + 2*lc] = make_uint2(f2tf(p0), f2tf(p1));
            *(uint2*)&Ps[(wq + lqr + 8)*AST + nt*8 + 2*lc] = make_uint2(f2tf(p2), f2tf(p3));
        }
        sum0 += __shfl_xor_sync(0xffffffffu, sum0, 1);
        sum0 += __shfl_xor_sync(0xffffffffu, sum0, 2);
        sum1 += __shfl_xor_sync(0xffffffffu, sum1, 1);
        sum1 += __shfl_xor_sync(0xffffffffu, sum1, 2);
        lrow0 = lrow0 * al0 + sum0;  mrow0 = nm0;
        lrow1 = lrow1 * al1 + sum1;  mrow1 = nm1;
        #pragma unroll
        for (int nt = 0; nt < 8; nt++) {
            oacc[nt][0] *= al0; oacc[nt][1] *= al0;
            oacc[nt][2] *= al1; oacc[nt][3] *= al1;
        }
        __syncwarp();

        // ---- O += P @ V ----
        #pragma unroll
        for (int ks = 0; ks < 8; ks++) {
            const int k0 = ks * 8;
            uint32_t af[4];
            ldsm_x4(af, sbP + 4u*(wq*AST + k0 + aoff));
            #pragma unroll
            for (int p = 0; p < 4; p++) {
                uint32_t bf[4];
                ldsm_x4(bf, bV + 4u*(p*16*AST + k0 + boff));
                mma_tf32(oacc[2*p],   af, bf,   oacc[2*p]);
                mma_tf32(oacc[2*p+1], af, bf+2, oacc[2*p+1]);
            }
        }
        __syncthreads();
    }

    // ---- normalize, round to tf32 (feeds final GEMM), write ----
    float li0 = 1.0f / lrow0;
    float li1 = 1.0f / lrow1;
    float* dst0 = O + ((size_t)(b*NN + n0q + wq + lqr    )) * CC + h * DD;
    float* dst1 = O + ((size_t)(b*NN + n0q + wq + lqr + 8)) * CC + h * DD;
    #pragma unroll
    for (int nt = 0; nt < 8; nt++) {
        uint2 o0 = make_uint2(f2tf(oacc[nt][0]*li0), f2tf(oacc[nt][1]*li0));
        uint2 o1 = make_uint2(f2tf(oacc[nt][2]*li1), f2tf(oacc[nt][3]*li1));
        *(uint2*)(dst0 + nt*8 + 2*lc) = o0;
        *(uint2*)(dst1 + nt*8 + 2*lc) = o1;
    }
}

// ---------------- launch ----------------
extern "C" void kernel_launch(void* const* d_in, const int* in_sizes, int n_in,
                              void* d_out, int out_size)
{
    const float* x_q = (const float*)d_in[0];
    const float* x_k = (const float*)d_in[1];
    const float* x_v = (const float*)d_in[2];
    const float* x_u = (const float*)d_in[3];
    const float* Wq  = (const float*)d_in[4];
    const float* Wk  = (const float*)d_in[5];
    const float* Wv  = (const float*)d_in[6];
    const float* Wp  = (const float*)d_in[7];
    const float* bp  = (const float*)d_in[8];
    float* out = (float*)d_out;

    float *q, *k, *vt, *ao, *uc, *xq, *xk, *xv, *wq, *wk, *wv, *wp;
    cudaGetSymbolAddress((void**)&q,  g_q);
    cudaGetSymbolAddress((void**)&k,  g_k);
    cudaGetSymbolAddress((void**)&vt, g_v);
    cudaGetSymbolAddress((void**)&ao, g_ao);
    cudaGetSymbolAddress((void**)&uc, g_uc);
    cudaGetSymbolAddress((void**)&xq, g_xq);
    cudaGetSymbolAddress((void**)&xk, g_xk);
    cudaGetSymbolAddress((void**)&xv, g_xv);
    cudaGetSymbolAddress((void**)&wq, g_wq);
    cudaGetSymbolAddress((void**)&wk, g_wk);
    cudaGetSymbolAddress((void**)&wv, g_wv);
    cudaGetSymbolAddress((void**)&wp, g_wp);

    cudaFuncSetAttribute(gemm_tc, cudaFuncAttributeMaxDynamicSharedMemorySize, GEMM_SMEM);
    cudaFuncSetAttribute(attn_tc, cudaFuncAttributeMaxDynamicSharedMemorySize, ATT_SMEM);

    // pre-round operands to tf32
    const int wn4 = CC*CC/4, xn4 = MTOT*CC/4;
    cvt_tf32<<<(wn4+255)/256, 256>>>(Wq, wq, wn4);
    cvt_tf32<<<(wn4+255)/256, 256>>>(Wk, wk, wn4);
    cvt_tf32<<<(wn4+255)/256, 256>>>(Wv, wv, wn4);
    cvt_tf32<<<(wn4+255)/256, 256>>>(Wp, wp, wn4);
    cvt_tf32<<<(xn4+255)/256, 256>>>(x_q, xq, xn4);
    cvt_tf32<<<(xn4+255)/256, 256>>>(x_k, xk, xn4);
    cvt_tf32<<<(xn4+255)/256, 256>>>(x_v, xv, xn4);

    // per-query uncertainty mean
    uc_kernel<<<(MTOT*32 + 255)/256, 256>>>(x_u);

    // projections (tf32 tensor cores); q folded with SCALE*uc; outputs pre-rounded
    dim3 ggrid(CC/128, MTOT/128);    // (6, 64)
    gemm_tc<<<ggrid, 256, GEMM_SMEM>>>(xq, wq, q,  uc,      SCALE_Q, nullptr, 0, 1);
    gemm_tc<<<ggrid, 256, GEMM_SMEM>>>(xk, wk, k,  nullptr, 1.0f,    nullptr, 0, 1);
    gemm_tc<<<ggrid, 256, GEMM_SMEM>>>(xv, wv, vt, nullptr, 1.0f,    nullptr, 1, 1);

    // flash attention
    dim3 agrid(NN/128, HH, BB);      // (16, 12, 4)
    attn_tc<<<agrid, 256, ATT_SMEM>>>(q, k, vt, ao);

    // output projection + bias (fp32 out)
    gemm_tc<<<ggrid, 256, GEMM_SMEM>>>(ao, wp, out, nullptr, 1.0f, bp, 0, 0);
}

// round 9
// speedup vs baseline: 6.6011x; 1.7781x over previous
#include <cuda_runtime.h>
#include <cuda_fp16.h>
#include <cstdint>

#define BB 4
#define NN 2048
#define CC 768
#define HH 12
#define DD 64
#define MTOT (BB*NN)          /* 8192 */
#define SCALE_Q 0.125f        /* 64^-0.5 */

// ---------------- scratch (no allocation allowed) ----------------
__device__ __half g_q [MTOT*CC];
__device__ __half g_k [MTOT*CC];
__device__ __half g_v [MTOT*CC];   // V TRANSPOSED: [B][H][D][N]
__device__ __half g_ao[MTOT*CC];
__device__ float  g_uc[MTOT];
__device__ __half g_xq[MTOT*CC];   // fp16-rounded inputs
__device__ __half g_xk[MTOT*CC];
__device__ __half g_xv[MTOT*CC];
__device__ __half g_wq[CC*CC];     // fp16-rounded weights
__device__ __half g_wk[CC*CC];
__device__ __half g_wv[CC*CC];
__device__ __half g_wp[CC*CC];

// ---------------- helpers ----------------
__device__ __forceinline__ uint32_t smem_u32(const void* p) {
    uint32_t a;
    asm("{ .reg .u64 t; cvta.to.shared.u64 t, %1; cvt.u32.u64 %0, t; }" : "=r"(a) : "l"(p));
    return a;
}
__device__ __forceinline__ void mma_f16(float* d, const uint32_t* a, const uint32_t* b, const float* c) {
    asm volatile("mma.sync.aligned.m16n8k16.row.col.f32.f16.f16.f32 "
        "{%0,%1,%2,%3}, {%4,%5,%6,%7}, {%8,%9}, {%10,%11,%12,%13};\n"
        : "=f"(d[0]), "=f"(d[1]), "=f"(d[2]), "=f"(d[3])
        : "r"(a[0]), "r"(a[1]), "r"(a[2]), "r"(a[3]),
          "r"(b[0]), "r"(b[1]),
          "f"(c[0]), "f"(c[1]), "f"(c[2]), "f"(c[3]));
}
__device__ __forceinline__ void ldsm_x4(uint32_t* r, uint32_t saddr) {
    asm volatile("ldmatrix.sync.aligned.m8n8.x4.shared.b16 {%0,%1,%2,%3}, [%4];"
        : "=r"(r[0]), "=r"(r[1]), "=r"(r[2]), "=r"(r[3]) : "r"(saddr));
}
__device__ __forceinline__ void cpasync16(uint32_t dst, const void* src) {
    asm volatile("cp.async.cg.shared.global [%0], [%1], 16;" :: "r"(dst), "l"(src));
}
#define CP_COMMIT() asm volatile("cp.async.commit_group;" ::: "memory")
#define CP_WAIT(n)  asm volatile("cp.async.wait_group %0;" :: "n"(n) : "memory")
__device__ __forceinline__ uint32_t packh2(float lo, float hi) {
    __half2 h = __floats2half2_rn(lo, hi);
    return *(uint32_t*)&h;
}

// fragment lane offsets (in HALF units), stride S (halfs)
#define AOFFH(lane, S) ((((lane)&7) + (((lane)>>3)&1)*8)*(S) + (((lane)>>4)&1)*8)
#define BOFFH(lane, S) ((((lane)&7) + (((lane)>>4)&1)*8)*(S) + (((lane)>>3)&1)*8)

// ---------------- fp16 pre-round ----------------
__global__ void cvt_f16(const float* __restrict__ src, __half* __restrict__ dst, int n4)
{
    int i = blockIdx.x * blockDim.x + threadIdx.x;
    if (i < n4) {
        float4 v = *(const float4*)(src + (size_t)i*4);
        __half2 a = __floats2half2_rn(v.x, v.y);
        __half2 b = __floats2half2_rn(v.z, v.w);
        uint2 o = make_uint2(*(uint32_t*)&a, *(uint32_t*)&b);
        *(uint2*)(dst + (size_t)i*4) = o;
    }
}

// ---------------- uc = mean(x_u, axis=-1), one warp per row ----------------
__global__ void uc_kernel(const float* __restrict__ xu)
{
    int gid  = blockIdx.x * blockDim.x + threadIdx.x;
    int row  = gid >> 5;
    int lane = gid & 31;
    if (row >= MTOT) return;
    const float* p = xu + (size_t)row * CC;
    float s = 0.f;
    #pragma unroll
    for (int i = 0; i < CC/32; i++) s += p[lane + 32*i];
    #pragma unroll
    for (int off = 16; off; off >>= 1) s += __shfl_down_sync(0xffffffffu, s, off);
    if (lane == 0) g_uc[row] = s * (1.0f / (float)CC);
}

// ================= fp16 mma GEMM: Y = X @ W^T =================
// BM=128, BN=128, BK=64 halfs, cp.async double-buffered. 8 warps (2m x 4n), warp 64x32.
#define GSTH 72
#define GEMM_SMEM (2*2*128*GSTH*2)   /* 73728 B */
__global__ __launch_bounds__(256, 2)
void gemm_tc(const __half* __restrict__ X, const __half* __restrict__ W,
             float* __restrict__ Yf, __half* __restrict__ Yh,
             const float* __restrict__ rowScale, float scaleConst,
             const float* __restrict__ bias, int vtMode)
{
    extern __shared__ __half gsm[];
    const int tid = threadIdx.x;
    const int wid = tid >> 5;
    const int lane = tid & 31;
    const int lq = lane >> 2;
    const int lc = lane & 3;
    const int wm = wid >> 2;      // 0..1
    const int wn = wid & 3;       // 0..3
    const int m0 = blockIdx.y * 128;
    const int n0 = blockIdx.x * 128;

    const uint32_t sbA = smem_u32(gsm);
    const uint32_t sbB = sbA + 2u*2*128*GSTH;

    float acc[4][4][4];
    #pragma unroll
    for (int i = 0; i < 4; i++)
        #pragma unroll
        for (int j = 0; j < 4; j++)
            #pragma unroll
            for (int t = 0; t < 4; t++) acc[i][j][t] = 0.f;

    auto issue = [&](int s, int buf) {
        const int k0 = s * 64;
        #pragma unroll
        for (int i = 0; i < 4; i++) {
            int lin = tid + 256*i;          // 0..1023
            int row = lin >> 3, c8 = lin & 7;
            cpasync16(sbA + 2u*(buf*128*GSTH + row*GSTH + c8*8),
                      X + (size_t)(m0+row)*CC + k0 + c8*8);
            cpasync16(sbB + 2u*(buf*128*GSTH + row*GSTH + c8*8),
                      W + (size_t)(n0+row)*CC + k0 + c8*8);
        }
        CP_COMMIT();
    };

    const int NSTAGE = CC / 64;   // 12
    issue(0, 0);
    #pragma unroll 1
    for (int s = 0; s < NSTAGE; s++) {
        const int cur = s & 1;
        if (s + 1 < NSTAGE) { issue(s + 1, cur ^ 1); CP_WAIT(1); }
        else                { CP_WAIT(0); }
        __syncthreads();
        const uint32_t baseA = sbA + 2u*(cur*128*GSTH + wm*64*GSTH + AOFFH(lane, GSTH));
        const uint32_t baseB = sbB + 2u*(cur*128*GSTH + wn*32*GSTH + BOFFH(lane, GSTH));
        #pragma unroll
        for (int ks = 0; ks < 4; ks++) {
            uint32_t af[4][4];
            #pragma unroll
            for (int mi = 0; mi < 4; mi++)
                ldsm_x4(af[mi], baseA + 2u*(mi*16*GSTH + ks*16));
            uint32_t bf[2][4];
            #pragma unroll
            for (int p = 0; p < 2; p++)
                ldsm_x4(bf[p], baseB + 2u*(p*16*GSTH + ks*16));
            #pragma unroll
            for (int nj = 0; nj < 4; nj++)
                #pragma unroll
                for (int mi = 0; mi < 4; mi++)
                    mma_f16(acc[mi][nj], af[mi], &bf[nj>>1][(nj&1)*2], acc[mi][nj]);
        }
        __syncthreads();
    }

    // epilogue
    #pragma unroll
    for (int mi = 0; mi < 4; mi++) {
        int row0 = m0 + wm*64 + mi*16 + lq;
        int row1 = row0 + 8;
        float rs0 = scaleConst, rs1 = scaleConst;
        if (rowScale) { rs0 *= rowScale[row0]; rs1 *= rowScale[row1]; }
        #pragma unroll
        for (int nj = 0; nj < 4; nj++) {
            int col = n0 + wn*32 + nj*8 + 2*lc;
            float v0 = acc[mi][nj][0]*rs0, v1 = acc[mi][nj][1]*rs0;
            float v2 = acc[mi][nj][2]*rs1, v3 = acc[mi][nj][3]*rs1;
            if (Yf) {   // fp32 out + bias (final projection)
                float b0 = bias[col], b1 = bias[col+1];
                *(float2*)(Yf + (size_t)row0 * CC + col) = make_float2(v0 + b0, v1 + b1);
                *(float2*)(Yf + (size_t)row1 * CC + col) = make_float2(v2 + b0, v3 + b1);
            } else if (!vtMode) {
                uint32_t h0 = packh2(v0, v1), h1 = packh2(v2, v3);
                *(uint32_t*)(Yh + (size_t)row0 * CC + col) = h0;
                *(uint32_t*)(Yh + (size_t)row1 * CC + col) = h1;
            } else {
                int h = col >> 6, d = col & 63;
                int b0i = row0 >> 11, n0i = row0 & 2047;
                int b1i = row1 >> 11, n1i = row1 & 2047;
                __half* base0 = Yh + ((size_t)(b0i*HH + h)*DD) * NN;
                __half* base1 = Yh + ((size_t)(b1i*HH + h)*DD) * NN;
                base0[(size_t)d*NN + n0i]     = __float2half_rn(v0);
                base0[(size_t)(d+1)*NN + n0i] = __float2half_rn(v1);
                base1[(size_t)d*NN + n1i]     = __float2half_rn(v2);
                base1[(size_t)(d+1)*NN + n1i] = __float2half_rn(v3);
            }
        }
    }
}

// ================= flash attention: fp16 mma, P stays in registers =================
// grid (NN/128, HH, BB), 256 threads = 8 warps, each warp 16 q rows.
#define AST 72
// halfs: K[2][64][AST] | V[2][64][AST] | Q[128][AST]
#define ATT_SMEM ((2*64*AST + 2*64*AST + 128*AST)*2)   /* 55296 B */
__global__ __launch_bounds__(256, 2)
void attn_tc(const __half* __restrict__ Q, const __half* __restrict__ K,
             const __half* __restrict__ Vt, __half* __restrict__ O)
{
    extern __shared__ __half smh[];
    const int tid  = threadIdx.x;
    const int wid  = tid >> 5;
    const int lane = tid & 31;
    const int lc   = lane & 3;
    const int lq   = lane >> 2;
    const int wq   = wid * 16;
    const int b    = blockIdx.z;
    const int h    = blockIdx.y;
    const int n0q  = blockIdx.x * 128;

    const uint32_t sbK = smem_u32(smh);
    const uint32_t sbV = sbK + 2u*2*64*AST;
    const uint32_t sbQ = sbV + 2u*2*64*AST;

    const __half* Qb  = Q + ((size_t)(b*NN + n0q)) * CC + h * DD;
    const __half* Kb  = K + ((size_t)b * NN) * CC + h * DD;
    const __half* Vtb = Vt + ((size_t)(b*HH + h) * DD) * NN;

    // stage Q (128x64 halfs)
    #pragma unroll
    for (int i = 0; i < 4; i++) {
        int lin = tid + 256*i;          // 0..1023
        int row = lin >> 3, c8 = lin & 7;
        cpasync16(sbQ + 2u*(row*AST + c8*8), Qb + (size_t)row*CC + c8*8);
    }
    CP_COMMIT();

    auto issueKV = [&](int kb, int buf) {
        #pragma unroll
        for (int i = 0; i < 2; i++) {
            int lin = tid + 256*i;      // 0..511
            int row = lin >> 3, c8 = lin & 7;
            cpasync16(sbK + 2u*(buf*64*AST + row*AST + c8*8),
                      Kb + (size_t)(kb*64 + row)*CC + c8*8);
            cpasync16(sbV + 2u*(buf*64*AST + row*AST + c8*8),
                      Vtb + (size_t)row*NN + kb*64 + c8*8);
        }
        CP_COMMIT();
    };

    issueKV(0, 0);
    CP_WAIT(1);            // Q staged
    __syncthreads();

    // Q fragments -> registers: qf[ks] covers d = ks*16..+15
    uint32_t qf[4][4];
    #pragma unroll
    for (int ks = 0; ks < 4; ks++)
        ldsm_x4(qf[ks], sbQ + 2u*(wq*AST + AOFFH(lane, AST) + ks*16));

    float oacc[8][4];
    #pragma unroll
    for (int i = 0; i < 8; i++)
        #pragma unroll
        for (int t = 0; t < 4; t++) oacc[i][t] = 0.f;
    float mrow0 = -1e30f, mrow1 = -1e30f, lrow0 = 0.f, lrow1 = 0.f;

    #pragma unroll 1
    for (int kb = 0; kb < NN/64; kb++) {
        const int cur = kb & 1;
        if (kb + 1 < NN/64) { issueKV(kb + 1, cur ^ 1); CP_WAIT(1); }
        else                { CP_WAIT(0); }
        __syncthreads();
        const uint32_t bK = sbK + 2u*(cur*64*AST) + 2u*BOFFH(lane, AST);
        const uint32_t bV = sbV + 2u*(cur*64*AST) + 2u*BOFFH(lane, AST);

        // ---- S = Q K^T : n-tiles = 8 key groups ----
        float sacc[8][4];
        #pragma unroll
        for (int i = 0; i < 8; i++)
            #pragma unroll
            for (int t = 0; t < 4; t++) sacc[i][t] = 0.f;
        #pragma unroll
        for (int ks = 0; ks < 4; ks++) {
            #pragma unroll
            for (int p = 0; p < 4; p++) {
                uint32_t bf[4];
                ldsm_x4(bf, bK + 2u*(p*16*AST + ks*16));
                mma_f16(sacc[2*p],   qf[ks], bf,   sacc[2*p]);
                mma_f16(sacc[2*p+1], qf[ks], bf+2, sacc[2*p+1]);
            }
        }

        // ---- online softmax (register-resident) ----
        float rmax0 = -1e30f, rmax1 = -1e30f;
        #pragma unroll
        for (int nt = 0; nt < 8; nt++) {
            rmax0 = fmaxf(rmax0, fmaxf(sacc[nt][0], sacc[nt][1]));
            rmax1 = fmaxf(rmax1, fmaxf(sacc[nt][2], sacc[nt][3]));
        }
        rmax0 = fmaxf(rmax0, __shfl_xor_sync(0xffffffffu, rmax0, 1));
        rmax0 = fmaxf(rmax0, __shfl_xor_sync(0xffffffffu, rmax0, 2));
        rmax1 = fmaxf(rmax1, __shfl_xor_sync(0xffffffffu, rmax1, 1));
        rmax1 = fmaxf(rmax1, __shfl_xor_sync(0xffffffffu, rmax1, 2));
        float nm0 = fmaxf(mrow0, rmax0);
        float nm1 = fmaxf(mrow1, rmax1);
        float al0 = __expf(mrow0 - nm0);
        float al1 = __expf(mrow1 - nm1);
        float sum0 = 0.f, sum1 = 0.f;
        #pragma unroll
        for (int nt = 0; nt < 8; nt++) {
            sacc[nt][0] = __expf(sacc[nt][0] - nm0);
            sacc[nt][1] = __expf(sacc[nt][1] - nm0);
            sacc[nt][2] = __expf(sacc[nt][2] - nm1);
            sacc[nt][3] = __expf(sacc[nt][3] - nm1);
            sum0 += sacc[nt][0] + sacc[nt][1];
            sum1 += sacc[nt][2] + sacc[nt][3];
        }
        sum0 += __shfl_xor_sync(0xffffffffu, sum0, 1);
        sum0 += __shfl_xor_sync(0xffffffffu, sum0, 2);
        sum1 += __shfl_xor_sync(0xffffffffu, sum1, 1);
        sum1 += __shfl_xor_sync(0xffffffffu, sum1, 2);
        lrow0 = lrow0 * al0 + sum0;  mrow0 = nm0;
        lrow1 = lrow1 * al1 + sum1;  mrow1 = nm1;
        #pragma unroll
        for (int nt = 0; nt < 8; nt++) {
            oacc[nt][0] *= al0; oacc[nt][1] *= al0;
            oacc[nt][2] *= al1; oacc[nt][3] *= al1;
        }

        // ---- O += P @ V : P packed straight from registers ----
        #pragma unroll
        for (int ks = 0; ks < 4; ks++) {
            uint32_t af[4];
            af[0] = packh2(sacc[2*ks][0],   sacc[2*ks][1]);
            af[1] = packh2(sacc[2*ks][2],   sacc[2*ks][3]);
            af[2] = packh2(sacc[2*ks+1][0], sacc[2*ks+1][1]);
            af[3] = packh2(sacc[2*ks+1][2], sacc[2*ks+1][3]);
            #pragma unroll
            for (int p = 0; p < 4; p++) {
                uint32_t bf[4];
                ldsm_x4(bf, bV + 2u*(p*16*AST + ks*16));
                mma_f16(oacc[2*p],   af, bf,   oacc[2*p]);
                mma_f16(oacc[2*p+1], af, bf+2, oacc[2*p+1]);
            }
        }
        __syncthreads();
    }

    // ---- normalize and write (fp16) ----
    float li0 = 1.0f / lrow0;
    float li1 = 1.0f / lrow1;
    __half* dst0 = O + ((size_t)(b*NN + n0q + wq + lq    )) * CC + h * DD;
    __half* dst1 = O + ((size_t)(b*NN + n0q + wq + lq + 8)) * CC + h * DD;
    #pragma unroll
    for (int nt = 0; nt < 8; nt++) {
        *(uint32_t*)(dst0 + nt*8 + 2*lc) = packh2(oacc[nt][0]*li0, oacc[nt][1]*li0);
        *(uint32_t*)(dst1 + nt*8 + 2*lc) = packh2(oacc[nt][2]*li1, oacc[nt][3]*li1);
    }
}

// ---------------- launch ----------------
extern "C" void kernel_launch(void* const* d_in, const int* in_sizes, int n_in,
                              void* d_out, int out_size)
{
    const float* x_q = (const float*)d_in[0];
    const float* x_k = (const float*)d_in[1];
    const float* x_v = (const float*)d_in[2];
    const float* x_u = (const float*)d_in[3];
    const float* Wq  = (const float*)d_in[4];
    const float* Wk  = (const float*)d_in[5];
    const float* Wv  = (const float*)d_in[6];
    const float* Wp  = (const float*)d_in[7];
    const float* bp  = (const float*)d_in[8];
    float* out = (float*)d_out;

    __half *q, *k, *vt, *ao, *xq, *xk, *xv, *wq, *wk, *wv, *wp;
    float *uc;
    cudaGetSymbolAddress((void**)&q,  g_q);
    cudaGetSymbolAddress((void**)&k,  g_k);
    cudaGetSymbolAddress((void**)&vt, g_v);
    cudaGetSymbolAddress((void**)&ao, g_ao);
    cudaGetSymbolAddress((void**)&uc, g_uc);
    cudaGetSymbolAddress((void**)&xq, g_xq);
    cudaGetSymbolAddress((void**)&xk, g_xk);
    cudaGetSymbolAddress((void**)&xv, g_xv);
    cudaGetSymbolAddress((void**)&wq, g_wq);
    cudaGetSymbolAddress((void**)&wk, g_wk);
    cudaGetSymbolAddress((void**)&wv, g_wv);
    cudaGetSymbolAddress((void**)&wp, g_wp);

    cudaFuncSetAttribute(gemm_tc, cudaFuncAttributeMaxDynamicSharedMemorySize, GEMM_SMEM);
    cudaFuncSetAttribute(attn_tc, cudaFuncAttributeMaxDynamicSharedMemorySize, ATT_SMEM);

    // pre-round operands to fp16
    const int wn4 = CC*CC/4, xn4 = MTOT*CC/4;
    cvt_f16<<<(wn4+255)/256, 256>>>(Wq, wq, wn4);
    cvt_f16<<<(wn4+255)/256, 256>>>(Wk, wk, wn4);
    cvt_f16<<<(wn4+255)/256, 256>>>(Wv, wv, wn4);
    cvt_f16<<<(wn4+255)/256, 256>>>(Wp, wp, wn4);
    cvt_f16<<<(xn4+255)/256, 256>>>(x_q, xq, xn4);
    cvt_f16<<<(xn4+255)/256, 256>>>(x_k, xk, xn4);
    cvt_f16<<<(xn4+255)/256, 256>>>(x_v, xv, xn4);

    // per-query uncertainty mean
    uc_kernel<<<(MTOT*32 + 255)/256, 256>>>(x_u);

    // projections (fp16 tensor cores); q folded with SCALE*uc; V written transposed
    dim3 ggrid(CC/128, MTOT/128);    // (6, 64)
    gemm_tc<<<ggrid, 256, GEMM_SMEM>>>(xq, wq, nullptr, q,  uc,      SCALE_Q, nullptr, 0);
    gemm_tc<<<ggrid, 256, GEMM_SMEM>>>(xk, wk, nullptr, k,  nullptr, 1.0f,    nullptr, 0);
    gemm_tc<<<ggrid, 256, GEMM_SMEM>>>(xv, wv, nullptr, vt, nullptr, 1.0f,    nullptr, 1);

    // flash attention (fp16 tensor cores, P in registers)
    dim3 agrid(NN/128, HH, BB);      // (16, 12, 4)
    attn_tc<<<agrid, 256, ATT_SMEM>>>(q, k, vt, ao);

    // output projection + bias (fp32 out)
    gemm_tc<<<ggrid, 256, GEMM_SMEM>>>(ao, wp, out, nullptr, nullptr, 1.0f, bp, 0);
}

// round 10
// speedup vs baseline: 7.5127x; 1.1381x over previous
#include <cuda_runtime.h>
#include <cuda_fp16.h>
#include <cstdint>

#define BB 4
#define NN 2048
#define CC 768
#define HH 12
#define DD 64
#define MTOT (BB*NN)          /* 8192 */
#define SCALE_Q 0.125f        /* 64^-0.5 */

// ---------------- scratch (no allocation allowed) ----------------
__device__ __half g_q [MTOT*CC];
__device__ __half g_k [MTOT*CC];
__device__ __half g_v [MTOT*CC];   // V TRANSPOSED: [B][H][D][N]
__device__ __half g_ao[MTOT*CC];
__device__ float  g_uc[MTOT];
__device__ __half g_xq[MTOT*CC];
__device__ __half g_xk[MTOT*CC];
__device__ __half g_xv[MTOT*CC];
__device__ __half g_wq[CC*CC];
__device__ __half g_wk[CC*CC];
__device__ __half g_wv[CC*CC];
__device__ __half g_wp[CC*CC];

// ---------------- helpers ----------------
__device__ __forceinline__ uint32_t smem_u32(const void* p) {
    uint32_t a;
    asm("{ .reg .u64 t; cvta.to.shared.u64 t, %1; cvt.u32.u64 %0, t; }" : "=r"(a) : "l"(p));
    return a;
}
__device__ __forceinline__ void mma_f16(float* d, const uint32_t* a, const uint32_t* b, const float* c) {
    asm volatile("mma.sync.aligned.m16n8k16.row.col.f32.f16.f16.f32 "
        "{%0,%1,%2,%3}, {%4,%5,%6,%7}, {%8,%9}, {%10,%11,%12,%13};\n"
        : "=f"(d[0]), "=f"(d[1]), "=f"(d[2]), "=f"(d[3])
        : "r"(a[0]), "r"(a[1]), "r"(a[2]), "r"(a[3]),
          "r"(b[0]), "r"(b[1]),
          "f"(c[0]), "f"(c[1]), "f"(c[2]), "f"(c[3]));
}
__device__ __forceinline__ void ldsm_x4(uint32_t* r, uint32_t saddr) {
    asm volatile("ldmatrix.sync.aligned.m8n8.x4.shared.b16 {%0,%1,%2,%3}, [%4];"
        : "=r"(r[0]), "=r"(r[1]), "=r"(r[2]), "=r"(r[3]) : "r"(saddr));
}
__device__ __forceinline__ void cpasync16(uint32_t dst, const void* src) {
    asm volatile("cp.async.cg.shared.global [%0], [%1], 16;" :: "r"(dst), "l"(src));
}
#define CP_COMMIT() asm volatile("cp.async.commit_group;" ::: "memory")
#define CP_WAIT(n)  asm volatile("cp.async.wait_group %0;" :: "n"(n) : "memory")
__device__ __forceinline__ uint32_t packh2(float lo, float hi) {
    __half2 h = __floats2half2_rn(lo, hi);
    return *(uint32_t*)&h;
}
#define AOFFH(lane, S) ((((lane)&7) + (((lane)>>3)&1)*8)*(S) + (((lane)>>4)&1)*8)
#define BOFFH(lane, S) ((((lane)&7) + (((lane)>>4)&1)*8)*(S) + (((lane)>>3)&1)*8)

// ---------------- fused fp16 pre-round: 3 inputs / 4 weights ----------------
__global__ void cvt3_f16(const float* __restrict__ a, const float* __restrict__ b,
                         const float* __restrict__ c,
                         __half* __restrict__ oa, __half* __restrict__ ob,
                         __half* __restrict__ oc, int n4)
{
    int i = blockIdx.x * blockDim.x + threadIdx.x;
    if (i >= n4) return;
    const float* s = (blockIdx.y == 0) ? a : (blockIdx.y == 1) ? b : c;
    __half* d      = (blockIdx.y == 0) ? oa : (blockIdx.y == 1) ? ob : oc;
    float4 v = *(const float4*)(s + (size_t)i*4);
    __half2 h0 = __floats2half2_rn(v.x, v.y);
    __half2 h1 = __floats2half2_rn(v.z, v.w);
    *(uint2*)(d + (size_t)i*4) = make_uint2(*(uint32_t*)&h0, *(uint32_t*)&h1);
}
__global__ void cvt4_f16(const float* __restrict__ a, const float* __restrict__ b,
                         const float* __restrict__ c, const float* __restrict__ e,
                         __half* __restrict__ oa, __half* __restrict__ ob,
                         __half* __restrict__ oc, __half* __restrict__ oe, int n4)
{
    int i = blockIdx.x * blockDim.x + threadIdx.x;
    if (i >= n4) return;
    const float* s = (blockIdx.y == 0) ? a : (blockIdx.y == 1) ? b : (blockIdx.y == 2) ? c : e;
    __half* d      = (blockIdx.y == 0) ? oa : (blockIdx.y == 1) ? ob : (blockIdx.y == 2) ? oc : oe;
    float4 v = *(const float4*)(s + (size_t)i*4);
    __half2 h0 = __floats2half2_rn(v.x, v.y);
    __half2 h1 = __floats2half2_rn(v.z, v.w);
    *(uint2*)(d + (size_t)i*4) = make_uint2(*(uint32_t*)&h0, *(uint32_t*)&h1);
}

// ---------------- uc = mean(x_u, axis=-1), one warp per row ----------------
__global__ void uc_kernel(const float* __restrict__ xu)
{
    int gid  = blockIdx.x * blockDim.x + threadIdx.x;
    int row  = gid >> 5;
    int lane = gid & 31;
    if (row >= MTOT) return;
    const float* p = xu + (size_t)row * CC;
    float s = 0.f;
    #pragma unroll
    for (int i = 0; i < CC/32; i++) s += p[lane + 32*i];
    #pragma unroll
    for (int off = 16; off; off >>= 1) s += __shfl_down_sync(0xffffffffu, s, off);
    if (lane == 0) g_uc[row] = s * (1.0f / (float)CC);
}

// ================= fp16 mma GEMM body: Y = X @ W^T =================
// BM=128, BN=128, BK=64 halfs, 3-stage cp.async, 1 barrier/stage.
#define GSTH 72
#define GSTAGE_W (128*GSTH)                 /* words per tensor per stage */
#define GEMM_SMEM (3*2*GSTAGE_W*2)          /* 110592 B */
__device__ __forceinline__ void gemm_body(
    const __half* __restrict__ X, const __half* __restrict__ W,
    float* __restrict__ Yf, __half* __restrict__ Yh,
    const float* __restrict__ rowScale, float scaleConst,
    const float* __restrict__ bias, int vtMode,
    __half* gsm, int m0, int n0)
{
    const int tid = threadIdx.x;
    const int wid = tid >> 5;
    const int lane = tid & 31;
    const int lq = lane >> 2;
    const int lc = lane & 3;
    const int wm = wid >> 2;
    const int wn = wid & 3;

    const uint32_t sbA = smem_u32(gsm);
    const uint32_t sbB = sbA + 2u*3*GSTAGE_W;

    float acc[4][4][4];
    #pragma unroll
    for (int i = 0; i < 4; i++)
        #pragma unroll
        for (int j = 0; j < 4; j++)
            #pragma unroll
            for (int t = 0; t < 4; t++) acc[i][j][t] = 0.f;

    auto issue = [&](int s, int buf) {
        const int k0 = s * 64;
        #pragma unroll
        for (int i = 0; i < 4; i++) {
            int lin = tid + 256*i;
            int row = lin >> 3, c8 = lin & 7;
            cpasync16(sbA + 2u*(buf*GSTAGE_W + row*GSTH + c8*8),
                      X + (size_t)(m0+row)*CC + k0 + c8*8);
            cpasync16(sbB + 2u*(buf*GSTAGE_W + row*GSTH + c8*8),
                      W + (size_t)(n0+row)*CC + k0 + c8*8);
        }
        CP_COMMIT();
    };

    const int NSTAGE = CC / 64;   // 12
    issue(0, 0);
    issue(1, 1);
    #pragma unroll 1
    for (int s = 0; s < NSTAGE; s++) {
        if (s + 1 < NSTAGE) { CP_WAIT(1); } else { CP_WAIT(0); }
        __syncthreads();
        const int cur = s % 3;
        const uint32_t baseA = sbA + 2u*(cur*GSTAGE_W + wm*64*GSTH + AOFFH(lane, GSTH));
        const uint32_t baseB = sbB + 2u*(cur*GSTAGE_W + wn*32*GSTH + BOFFH(lane, GSTH));
        #pragma unroll
        for (int ks = 0; ks < 4; ks++) {
            uint32_t af[4][4];
            #pragma unroll
            for (int mi = 0; mi < 4; mi++)
                ldsm_x4(af[mi], baseA + 2u*(mi*16*GSTH + ks*16));
            uint32_t bf[2][4];
            #pragma unroll
            for (int p = 0; p < 2; p++)
                ldsm_x4(bf[p], baseB + 2u*(p*16*GSTH + ks*16));
            #pragma unroll
            for (int nj = 0; nj < 4; nj++)
                #pragma unroll
                for (int mi = 0; mi < 4; mi++)
                    mma_f16(acc[mi][nj], af[mi], &bf[nj>>1][(nj&1)*2], acc[mi][nj]);
        }
        if (s + 2 < NSTAGE) issue(s + 2, (s + 2) % 3);
    }

    #pragma unroll
    for (int mi = 0; mi < 4; mi++) {
        int row0 = m0 + wm*64 + mi*16 + lq;
        int row1 = row0 + 8;
        float rs0 = scaleConst, rs1 = scaleConst;
        if (rowScale) { rs0 *= rowScale[row0]; rs1 *= rowScale[row1]; }
        #pragma unroll
        for (int nj = 0; nj < 4; nj++) {
            int col = n0 + wn*32 + nj*8 + 2*lc;
            float v0 = acc[mi][nj][0]*rs0, v1 = acc[mi][nj][1]*rs0;
            float v2 = acc[mi][nj][2]*rs1, v3 = acc[mi][nj][3]*rs1;
            if (Yf) {
                float b0 = bias[col], b1 = bias[col+1];
                *(float2*)(Yf + (size_t)row0 * CC + col) = make_float2(v0 + b0, v1 + b1);
                *(float2*)(Yf + (size_t)row1 * CC + col) = make_float2(v2 + b0, v3 + b1);
            } else if (!vtMode) {
                *(uint32_t*)(Yh + (size_t)row0 * CC + col) = packh2(v0, v1);
                *(uint32_t*)(Yh + (size_t)row1 * CC + col) = packh2(v2, v3);
            } else {
                int h = col >> 6, d = col & 63;
                int b0i = row0 >> 11, n0i = row0 & 2047;
                int b1i = row1 >> 11, n1i = row1 & 2047;
                __half* base0 = Yh + ((size_t)(b0i*HH + h)*DD) * NN;
                __half* base1 = Yh + ((size_t)(b1i*HH + h)*DD) * NN;
                base0[(size_t)d*NN + n0i]     = __float2half_rn(v0);
                base0[(size_t)(d+1)*NN + n0i] = __float2half_rn(v1);
                base1[(size_t)d*NN + n1i]     = __float2half_rn(v2);
                base1[(size_t)(d+1)*NN + n1i] = __float2half_rn(v3);
            }
        }
    }
}

// batched QKV projection: blockIdx.z selects {q,k,v}
__global__ __launch_bounds__(256, 2)
void gemm_qkv(const __half* __restrict__ xq, const __half* __restrict__ xk,
              const __half* __restrict__ xv,
              const __half* __restrict__ wq, const __half* __restrict__ wk,
              const __half* __restrict__ wv,
              __half* __restrict__ q, __half* __restrict__ k, __half* __restrict__ vt,
              const float* __restrict__ uc)
{
    extern __shared__ __half gsm[];
    const int z = blockIdx.z;
    const __half* X = (z == 0) ? xq : (z == 1) ? xk : xv;
    const __half* W = (z == 0) ? wq : (z == 1) ? wk : wv;
    __half* Y       = (z == 0) ? q  : (z == 1) ? k  : vt;
    gemm_body(X, W, nullptr, Y,
              (z == 0) ? uc : nullptr, (z == 0) ? SCALE_Q : 1.0f,
              nullptr, (z == 2) ? 1 : 0,
              gsm, blockIdx.y * 128, blockIdx.x * 128);
}

// final projection: fp32 out + bias
__global__ __launch_bounds__(256, 2)
void gemm_out(const __half* __restrict__ X, const __half* __restrict__ W,
              float* __restrict__ Y, const float* __restrict__ bias)
{
    extern __shared__ __half gsm[];
    gemm_body(X, W, Y, nullptr, nullptr, 1.0f, bias, 0,
              gsm, blockIdx.y * 128, blockIdx.x * 128);
}

// ================= flash attention: fp16 mma, P in regs, 3-stage KV =================
#define AST 72
#define KVW (64*AST)                         /* words per tensor per stage */
#define ATT_SMEM ((3*KVW*2 + 128*AST)*2)     /* 73728 B */
__global__ __launch_bounds__(256, 2)
void attn_tc(const __half* __restrict__ Q, const __half* __restrict__ K,
             const __half* __restrict__ Vt, __half* __restrict__ O)
{
    extern __shared__ __half smh[];
    const int tid  = threadIdx.x;
    const int wid  = tid >> 5;
    const int lane = tid & 31;
    const int lc   = lane & 3;
    const int lq   = lane >> 2;
    const int wq   = wid * 16;
    const int b    = blockIdx.z;
    const int h    = blockIdx.y;
    const int n0q  = blockIdx.x * 128;

    const uint32_t sbK = smem_u32(smh);
    const uint32_t sbV = sbK + 2u*3*KVW;
    const uint32_t sbQ = sbV + 2u*3*KVW;

    const __half* Qb  = Q + ((size_t)(b*NN + n0q)) * CC + h * DD;
    const __half* Kb  = K + ((size_t)b * NN) * CC + h * DD;
    const __half* Vtb = Vt + ((size_t)(b*HH + h) * DD) * NN;

    // group 0: Q (128x64 halfs)
    #pragma unroll
    for (int i = 0; i < 4; i++) {
        int lin = tid + 256*i;
        int row = lin >> 3, c8 = lin & 7;
        cpasync16(sbQ + 2u*(row*AST + c8*8), Qb + (size_t)row*CC + c8*8);
    }
    CP_COMMIT();

    auto issueKV = [&](int kb, int buf) {
        #pragma unroll
        for (int i = 0; i < 2; i++) {
            int lin = tid + 256*i;
            int row = lin >> 3, c8 = lin & 7;
            cpasync16(sbK + 2u*(buf*KVW + row*AST + c8*8),
                      Kb + (size_t)(kb*64 + row)*CC + c8*8);
            cpasync16(sbV + 2u*(buf*KVW + row*AST + c8*8),
                      Vtb + (size_t)row*NN + kb*64 + c8*8);
        }
        CP_COMMIT();
    };

    issueKV(0, 0);
    issueKV(1, 1);
    CP_WAIT(2);            // Q done (KV0, KV1 may be in flight)
    __syncthreads();

    uint32_t qf[4][4];
    #pragma unroll
    for (int ks = 0; ks < 4; ks++)
        ldsm_x4(qf[ks], sbQ + 2u*(wq*AST + AOFFH(lane, AST) + ks*16));

    float oacc[8][4];
    #pragma unroll
    for (int i = 0; i < 8; i++)
        #pragma unroll
        for (int t = 0; t < 4; t++) oacc[i][t] = 0.f;
    float mrow0 = -1e30f, mrow1 = -1e30f, lrow0 = 0.f, lrow1 = 0.f;

    const int NB = NN/64;  // 32
    #pragma unroll 1
    for (int kb = 0; kb < NB; kb++) {
        if (kb + 1 < NB) { CP_WAIT(1); } else { CP_WAIT(0); }
        __syncthreads();
        const int cur = kb % 3;
        const uint32_t bK = sbK + 2u*(cur*KVW) + 2u*BOFFH(lane, AST);
        const uint32_t bV = sbV + 2u*(cur*KVW) + 2u*BOFFH(lane, AST);

        // ---- S = Q K^T ----
        float sacc[8][4];
        #pragma unroll
        for (int i = 0; i < 8; i++)
            #pragma unroll
            for (int t = 0; t < 4; t++) sacc[i][t] = 0.f;
        #pragma unroll
        for (int ks = 0; ks < 4; ks++) {
            #pragma unroll
            for (int p = 0; p < 4; p++) {
                uint32_t bf[4];
                ldsm_x4(bf, bK + 2u*(p*16*AST + ks*16));
                mma_f16(sacc[2*p],   qf[ks], bf,   sacc[2*p]);
                mma_f16(sacc[2*p+1], qf[ks], bf+2, sacc[2*p+1]);
            }
        }

        // ---- online softmax (register-resident) ----
        float rmax0 = -1e30f, rmax1 = -1e30f;
        #pragma unroll
        for (int nt = 0; nt < 8; nt++) {
            rmax0 = fmaxf(rmax0, fmaxf(sacc[nt][0], sacc[nt][1]));
            rmax1 = fmaxf(rmax1, fmaxf(sacc[nt][2], sacc[nt][3]));
        }
        rmax0 = fmaxf(rmax0, __shfl_xor_sync(0xffffffffu, rmax0, 1));
        rmax0 = fmaxf(rmax0, __shfl_xor_sync(0xffffffffu, rmax0, 2));
        rmax1 = fmaxf(rmax1, __shfl_xor_sync(0xffffffffu, rmax1, 1));
        rmax1 = fmaxf(rmax1, __shfl_xor_sync(0xffffffffu, rmax1, 2));
        float nm0 = fmaxf(mrow0, rmax0);
        float nm1 = fmaxf(mrow1, rmax1);
        float al0 = __expf(mrow0 - nm0);
        float al1 = __expf(mrow1 - nm1);
        float sum0 = 0.f, sum1 = 0.f;
        #pragma unroll
        for (int nt = 0; nt < 8; nt++) {
            sacc[nt][0] = __expf(sacc[nt][0] - nm0);
            sacc[nt][1] = __expf(sacc[nt][1] - nm0);
            sacc[nt][2] = __expf(sacc[nt][2] - nm1);
            sacc[nt][3] = __expf(sacc[nt][3] - nm1);
            sum0 += sacc[nt][0] + sacc[nt][1];
            sum1 += sacc[nt][2] + sacc[nt][3];
        }
        sum0 += __shfl_xor_sync(0xffffffffu, sum0, 1);
        sum0 += __shfl_xor_sync(0xffffffffu, sum0, 2);
        sum1 += __shfl_xor_sync(0xffffffffu, sum1, 1);
        sum1 += __shfl_xor_sync(0xffffffffu, sum1, 2);
        lrow0 = lrow0 * al0 + sum0;  mrow0 = nm0;
        lrow1 = lrow1 * al1 + sum1;  mrow1 = nm1;
        #pragma unroll
        for (int nt = 0; nt < 8; nt++) {
            oacc[nt][0] *= al0; oacc[nt][1] *= al0;
            oacc[nt][2] *= al1; oacc[nt][3] *= al1;
        }

        // ---- O += P @ V : P packed straight from registers ----
        #pragma unroll
        for (int ks = 0; ks < 4; ks++) {
            uint32_t af[4];
            af[0] = packh2(sacc[2*ks][0],   sacc[2*ks][1]);
            af[1] = packh2(sacc[2*ks][2],   sacc[2*ks][3]);
            af[2] = packh2(sacc[2*ks+1][0], sacc[2*ks+1][1]);
            af[3] = packh2(sacc[2*ks+1][2], sacc[2*ks+1][3]);
            #pragma unroll
            for (int p = 0; p < 4; p++) {
                uint32_t bf[4];
                ldsm_x4(bf, bV + 2u*(p*16*AST + ks*16));
                mma_f16(oacc[2*p],   af, bf,   oacc[2*p]);
                mma_f16(oacc[2*p+1], af, bf+2, oacc[2*p+1]);
            }
        }
        if (kb + 2 < NB) issueKV(kb + 2, (kb + 2) % 3);
    }

    // ---- normalize and write (fp16) ----
    float li0 = 1.0f / lrow0;
    float li1 = 1.0f / lrow1;
    __half* dst0 = O + ((size_t)(b*NN + n0q + wq + lq    )) * CC + h * DD;
    __half* dst1 = O + ((size_t)(b*NN + n0q + wq + lq + 8)) * CC + h * DD;
    #pragma unroll
    for (int nt = 0; nt < 8; nt++) {
        *(uint32_t*)(dst0 + nt*8 + 2*lc) = packh2(oacc[nt][0]*li0, oacc[nt][1]*li0);
        *(uint32_t*)(dst1 + nt*8 + 2*lc) = packh2(oacc[nt][2]*li1, oacc[nt][3]*li1);
    }
}

// ---------------- launch ----------------
extern "C" void kernel_launch(void* const* d_in, const int* in_sizes, int n_in,
                              void* d_out, int out_size)
{
    const float* x_q = (const float*)d_in[0];
    const float* x_k = (const float*)d_in[1];
    const float* x_v = (const float*)d_in[2];
    const float* x_u = (const float*)d_in[3];
    const float* Wq  = (const float*)d_in[4];
    const float* Wk  = (const float*)d_in[5];
    const float* Wv  = (const float*)d_in[6];
    const float* Wp  = (const float*)d_in[7];
    const float* bp  = (const float*)d_in[8];
    float* out = (float*)d_out;

    __half *q, *k, *vt, *ao, *xq, *xk, *xv, *wq, *wk, *wv, *wp;
    float *uc;
    cudaGetSymbolAddress((void**)&q,  g_q);
    cudaGetSymbolAddress((void**)&k,  g_k);
    cudaGetSymbolAddress((void**)&vt, g_v);
    cudaGetSymbolAddress((void**)&ao, g_ao);
    cudaGetSymbolAddress((void**)&uc, g_uc);
    cudaGetSymbolAddress((void**)&xq, g_xq);
    cudaGetSymbolAddress((void**)&xk, g_xk);
    cudaGetSymbolAddress((void**)&xv, g_xv);
    cudaGetSymbolAddress((void**)&wq, g_wq);
    cudaGetSymbolAddress((void**)&wk, g_wk);
    cudaGetSymbolAddress((void**)&wv, g_wv);
    cudaGetSymbolAddress((void**)&wp, g_wp);

    cudaFuncSetAttribute(gemm_qkv, cudaFuncAttributeMaxDynamicSharedMemorySize, GEMM_SMEM);
    cudaFuncSetAttribute(gemm_out, cudaFuncAttributeMaxDynamicSharedMemorySize, GEMM_SMEM);
    cudaFuncSetAttribute(attn_tc,  cudaFuncAttributeMaxDynamicSharedMemorySize, ATT_SMEM);

    // fused pre-round to fp16
    const int wn4 = CC*CC/4, xn4 = MTOT*CC/4;
    dim3 cg3((xn4 + 255)/256, 3);
    cvt3_f16<<<cg3, 256>>>(x_q, x_k, x_v, xq, xk, xv, xn4);
    dim3 cg4((wn4 + 255)/256, 4);
    cvt4_f16<<<cg4, 256>>>(Wq, Wk, Wv, Wp, wq, wk, wv, wp, wn4);

    // per-query uncertainty mean
    uc_kernel<<<(MTOT*32 + 255)/256, 256>>>(x_u);

    // batched QKV projections (fp16 tensor cores)
    dim3 ggrid(CC/128, MTOT/128, 3);   // (6, 64, 3) = 1152 CTAs
    gemm_qkv<<<ggrid, 256, GEMM_SMEM>>>(xq, xk, xv, wq, wk, wv, q, k, vt, uc);

    // flash attention
    dim3 agrid(NN/128, HH, BB);        // (16, 12, 4)
    attn_tc<<<agrid, 256, ATT_SMEM>>>(q, k, vt, ao);

    // output projection + bias (fp32 out)
    dim3 ogrid(CC/128, MTOT/128);
    gemm_out<<<ogrid, 256, GEMM_SMEM>>>(ao, wp, out, bp);
}